// round 3
// baseline (speedup 1.0000x reference)
#include <cuda_runtime.h>
#include <cstdint>
#include <cstddef>

#define B_ 32
#define S_ 128
#define T_ 128
#define V_ 32000
#define E_ 256
#define H_ 256
#define NEGV -1.0e9f

// ---------------- scratch (static device memory; no allocation) ----------------
__device__ float g_WhhT_enc[H_ * H_];
__device__ float g_WhhT_dec[H_ * H_];
__device__ float g_P_enc[B_ * S_ * H_];     // b_ih+b_hh + emb@W_ih^T  (encoder)
__device__ float g_P_dec[B_ * T_ * H_];
__device__ float g_enc_out[B_ * S_ * H_];
__device__ float g_h_final[B_ * H_];
__device__ float g_Hdec[B_ * T_ * H_];
__device__ float g_comb[B_ * T_ * 2 * H_];  // [context | h]
__device__ float g_attn_out[B_ * T_ * H_];

// ---------------- tiny transpose: out[k][j] = in[j][k], 256x256 ----------------
__global__ void k_transpose(const float* __restrict__ in, float* __restrict__ out) {
    int r = blockIdx.x;
    int c = threadIdx.x;
    out[c * H_ + r] = in[r * H_ + c];
}

// ---------------- generic fp32 GEMM: C[M,N] = gatherA[M,K] @ B[N,K]^T + bias (+tanh) ----
// A rows optionally gathered through gidx (embedding lookup fused).
// All dims must divide tile sizes (true for every call site here).
template <int BM, int BN, int BK, int TM, int TN>
__global__ __launch_bounds__(256) void k_gemm(
    int M, int N, int K,
    const float* __restrict__ A, const int* __restrict__ gidx,
    const float* __restrict__ Bm, float* __restrict__ C,
    const float* __restrict__ bias1, const float* __restrict__ bias2, int act) {
    constexpr int KV = BK / 4;        // float4 per smem row
    constexpr int RPP = 256 / KV;     // rows loaded per pass (64)
    constexpr int AP = BM / RPP;
    constexpr int BP = BN / RPP;

    __shared__ __align__(16) float As[2][BK][BM];
    __shared__ __align__(16) float Bs[2][BK][BN];

    const int tid = threadIdx.x;
    const int m0 = blockIdx.y * BM;
    const int n0 = blockIdx.x * BN;
    const int lr = tid / KV;   // 0..63
    const int lk = tid % KV;   // 0..KV-1

    const float* ap[AP];
    const float* bp[BP];
#pragma unroll
    for (int p = 0; p < AP; p++) {
        int gm = m0 + lr + p * RPP;
        int grow = gidx ? gidx[gm] : gm;
        ap[p] = A + (size_t)grow * K + lk * 4;
    }
#pragma unroll
    for (int p = 0; p < BP; p++)
        bp[p] = Bm + (size_t)(n0 + lr + p * RPP) * K + lk * 4;

    float acc[TM][TN];
#pragma unroll
    for (int i = 0; i < TM; i++)
#pragma unroll
        for (int j = 0; j < TN; j++) acc[i][j] = 0.0f;

    float4 ar[AP], br[BP];
#pragma unroll
    for (int p = 0; p < AP; p++) ar[p] = *(const float4*)(ap[p]);
#pragma unroll
    for (int p = 0; p < BP; p++) br[p] = *(const float4*)(bp[p]);
#pragma unroll
    for (int p = 0; p < AP; p++) {
        int m = lr + p * RPP;
        As[0][lk * 4 + 0][m] = ar[p].x;
        As[0][lk * 4 + 1][m] = ar[p].y;
        As[0][lk * 4 + 2][m] = ar[p].z;
        As[0][lk * 4 + 3][m] = ar[p].w;
    }
#pragma unroll
    for (int p = 0; p < BP; p++) {
        int n = lr + p * RPP;
        Bs[0][lk * 4 + 0][n] = br[p].x;
        Bs[0][lk * 4 + 1][n] = br[p].y;
        Bs[0][lk * 4 + 2][n] = br[p].z;
        Bs[0][lk * 4 + 3][n] = br[p].w;
    }
    __syncthreads();

    const int NT = K / BK;
    const int trow = tid / (BN / TN);
    const int tcol = tid % (BN / TN);

    for (int kt = 0; kt < NT; kt++) {
        const int cur = kt & 1;
        if (kt + 1 < NT) {
#pragma unroll
            for (int p = 0; p < AP; p++) ar[p] = *(const float4*)(ap[p] + (kt + 1) * BK);
#pragma unroll
            for (int p = 0; p < BP; p++) br[p] = *(const float4*)(bp[p] + (kt + 1) * BK);
        }
#pragma unroll
        for (int k = 0; k < BK; k++) {
            float a[TM], bf[TN];
#pragma unroll
            for (int i = 0; i < TM; i += 4) {
                float4 v = *(const float4*)&As[cur][k][trow * TM + i];
                a[i] = v.x; a[i + 1] = v.y; a[i + 2] = v.z; a[i + 3] = v.w;
            }
#pragma unroll
            for (int j = 0; j < TN; j += 4) {
                float4 v = *(const float4*)&Bs[cur][k][tcol * TN + j];
                bf[j] = v.x; bf[j + 1] = v.y; bf[j + 2] = v.z; bf[j + 3] = v.w;
            }
#pragma unroll
            for (int i = 0; i < TM; i++)
#pragma unroll
                for (int j = 0; j < TN; j++) acc[i][j] += a[i] * bf[j];
        }
        if (kt + 1 < NT) {
            const int nxt = cur ^ 1;
#pragma unroll
            for (int p = 0; p < AP; p++) {
                int m = lr + p * RPP;
                As[nxt][lk * 4 + 0][m] = ar[p].x;
                As[nxt][lk * 4 + 1][m] = ar[p].y;
                As[nxt][lk * 4 + 2][m] = ar[p].z;
                As[nxt][lk * 4 + 3][m] = ar[p].w;
            }
#pragma unroll
            for (int p = 0; p < BP; p++) {
                int n = lr + p * RPP;
                Bs[nxt][lk * 4 + 0][n] = br[p].x;
                Bs[nxt][lk * 4 + 1][n] = br[p].y;
                Bs[nxt][lk * 4 + 2][n] = br[p].z;
                Bs[nxt][lk * 4 + 3][n] = br[p].w;
            }
            __syncthreads();
        }
    }

    float bv[TN];
#pragma unroll
    for (int j = 0; j < TN; j++) {
        int n = n0 + tcol * TN + j;
        float v = bias1 ? bias1[n] : 0.0f;
        if (bias2) v += bias2[n];
        bv[j] = v;
    }
#pragma unroll
    for (int i = 0; i < TM; i++) {
        int m = m0 + trow * TM + i;
        float* crow = C + (size_t)m * N + n0 + tcol * TN;
#pragma unroll
        for (int j = 0; j < TN; j += 4) {
            float4 o;
            o.x = acc[i][j + 0] + bv[j + 0];
            o.y = acc[i][j + 1] + bv[j + 1];
            o.z = acc[i][j + 2] + bv[j + 2];
            o.w = acc[i][j + 3] + bv[j + 3];
            if (act) {
                o.x = tanhf(o.x); o.y = tanhf(o.y);
                o.z = tanhf(o.z); o.w = tanhf(o.w);
            }
            *(float4*)(crow + j) = o;
        }
    }
}

// ---------------- RNN recurrence: one CTA per batch element ----------------
// h_new = tanh(P[b,t,:] + h @ Whh^T), with optional length freezing (encoder)
// and optional copy of h into the upper half of g_comb (decoder).
__global__ __launch_bounds__(256) void k_rnn(
    const float* __restrict__ P, const float* __restrict__ WT,
    const int* __restrict__ lengths, const float* __restrict__ h0,
    float* __restrict__ outSeq, float* __restrict__ hFin,
    float* __restrict__ combHalf, int steps) {
    const int b = blockIdx.x;
    const int j = threadIdx.x;
    __shared__ __align__(16) float hs[H_];
    hs[j] = h0 ? h0[b * H_ + j] : 0.0f;
    __syncthreads();
    const int len = lengths ? lengths[b] : steps;
    const float* Pb = P + (size_t)b * steps * H_;
    float* Ob = outSeq + (size_t)b * steps * H_;
    const float* w = WT + j;

    for (int t = 0; t < steps; t++) {
        float a0 = 0.f, a1 = 0.f, a2 = 0.f, a3 = 0.f;
#pragma unroll 8
        for (int k = 0; k < H_; k += 4) {
            float4 h4 = *(const float4*)&hs[k];
            a0 += h4.x * w[(k + 0) * H_];
            a1 += h4.y * w[(k + 1) * H_];
            a2 += h4.z * w[(k + 2) * H_];
            a3 += h4.w * w[(k + 3) * H_];
        }
        float hn = tanhf(Pb[t * H_ + j] + ((a0 + a1) + (a2 + a3)));
        bool valid = t < len;
        __syncthreads();
        if (valid) hs[j] = hn;
        Ob[t * H_ + j] = valid ? hn : 0.0f;
        if (combHalf)
            combHalf[((size_t)(b * steps + t)) * (2 * H_) + H_ + j] = hn;
        __syncthreads();
    }
    if (hFin) hFin[b * H_ + j] = hs[j];
}

// ---------------- fused attention: scores -> softmax -> context ----------------
// CTA = (b, tile of 16 decoder steps). Writes context to g_comb[:, 0:H].
__global__ __launch_bounds__(256) void k_attn(
    const float* __restrict__ Hdec, const float* __restrict__ enc,
    const int* __restrict__ idx_de, float* __restrict__ comb) {
    const int b = blockIdx.x;
    const int t0 = blockIdx.y * 16;
    const int tid = threadIdx.x;
    __shared__ __align__(16) float hs[16][H_];
    __shared__ float sc[16][132];
    __shared__ int msk[S_];

    const float4* Hb4 = (const float4*)(Hdec + ((size_t)b * T_ + t0) * H_);
#pragma unroll
    for (int i = 0; i < 4; i++)
        ((float4*)hs)[tid + i * 256] = Hb4[tid + i * 256];
    if (tid < S_) msk[tid] = idx_de[b * S_ + tid];
    __syncthreads();

    const float* Eb = enc + (size_t)b * S_ * H_;

    // scores: thread (ti = tid/16, sg = tid%16), 8 source positions each
    {
        const int ti = tid >> 4, sg = tid & 15;
        const float4* h4 = (const float4*)hs[ti];
        for (int r = 0; r < 8; r++) {
            int s = r * 16 + sg;
            const float4* e4 = (const float4*)(Eb + s * H_);
            float a0 = 0.f, a1 = 0.f, a2 = 0.f, a3 = 0.f;
#pragma unroll 8
            for (int k = 0; k < H_ / 4; k++) {
                float4 e = e4[k], h = h4[k];
                a0 += e.x * h.x; a1 += e.y * h.y;
                a2 += e.z * h.z; a3 += e.w * h.w;
            }
            sc[ti][s] = (msk[s] == 0) ? NEGV : ((a0 + a1) + (a2 + a3));
        }
    }
    __syncthreads();

    // softmax: warp w handles rows 2w, 2w+1
    {
        const int w = tid >> 5, lane = tid & 31;
#pragma unroll
        for (int rr = 0; rr < 2; rr++) {
            int row = w * 2 + rr;
            float v0 = sc[row][lane], v1 = sc[row][lane + 32];
            float v2 = sc[row][lane + 64], v3 = sc[row][lane + 96];
            float m = fmaxf(fmaxf(v0, v1), fmaxf(v2, v3));
#pragma unroll
            for (int o = 16; o > 0; o >>= 1)
                m = fmaxf(m, __shfl_xor_sync(0xffffffffu, m, o));
            float e0 = expf(v0 - m), e1 = expf(v1 - m);
            float e2 = expf(v2 - m), e3 = expf(v3 - m);
            float sum = (e0 + e1) + (e2 + e3);
#pragma unroll
            for (int o = 16; o > 0; o >>= 1)
                sum += __shfl_xor_sync(0xffffffffu, sum, o);
            float inv = 1.0f / sum;
            sc[row][lane] = e0 * inv;
            sc[row][lane + 32] = e1 * inv;
            sc[row][lane + 64] = e2 * inv;
            sc[row][lane + 96] = e3 * inv;
        }
    }
    __syncthreads();

    // context: thread (ti = tid%16, jg = tid/16) accumulates 16 H-channels
    {
        const int ti = tid & 15, jg = tid >> 4;
        float4 c0 = {0, 0, 0, 0}, c1 = c0, c2 = c0, c3 = c0;
        for (int s = 0; s < S_; s++) {
            float p = sc[ti][s];
            const float4* e4 = (const float4*)(Eb + s * H_ + jg * 16);
            float4 e0 = e4[0], e1 = e4[1], e2 = e4[2], e3 = e4[3];
            c0.x += p * e0.x; c0.y += p * e0.y; c0.z += p * e0.z; c0.w += p * e0.w;
            c1.x += p * e1.x; c1.y += p * e1.y; c1.z += p * e1.z; c1.w += p * e1.w;
            c2.x += p * e2.x; c2.y += p * e2.y; c2.z += p * e2.z; c2.w += p * e2.w;
            c3.x += p * e3.x; c3.y += p * e3.y; c3.z += p * e3.z; c3.w += p * e3.w;
        }
        float* dst = comb + ((size_t)(b * T_ + t0 + ti)) * (2 * H_) + jg * 16;
        ((float4*)dst)[0] = c0;
        ((float4*)dst)[1] = c1;
        ((float4*)dst)[2] = c2;
        ((float4*)dst)[3] = c3;
    }
}

// ---------------- launch ----------------
extern "C" void kernel_launch(void* const* d_in, const int* in_sizes, int n_in,
                              void* d_out, int out_size) {
    const int* indices_de = (const int*)d_in[0];
    const int* lengths_de = (const int*)d_in[1];
    const int* indices_en = (const int*)d_in[2];
    /* lengths_en d_in[3] unused: all T valid */
    const float* emb_enc = (const float*)d_in[4];
    const float* emb_dec = (const float*)d_in[5];
    const float* W_ih_enc = (const float*)d_in[6];
    const float* W_hh_enc = (const float*)d_in[7];
    const float* b_ih_enc = (const float*)d_in[8];
    const float* b_hh_enc = (const float*)d_in[9];
    const float* W_ih_dec = (const float*)d_in[10];
    const float* W_hh_dec = (const float*)d_in[11];
    const float* b_ih_dec = (const float*)d_in[12];
    const float* b_hh_dec = (const float*)d_in[13];
    const float* W_attn = (const float*)d_in[14];
    const float* b_attn = (const float*)d_in[15];
    const float* W_out = (const float*)d_in[16];
    const float* b_out = (const float*)d_in[17];
    float* out = (float*)d_out;

    float *pWTe, *pWTd, *pPe, *pPd, *pEnc, *pHf, *pHd, *pComb, *pAo;
    cudaGetSymbolAddress((void**)&pWTe, g_WhhT_enc);
    cudaGetSymbolAddress((void**)&pWTd, g_WhhT_dec);
    cudaGetSymbolAddress((void**)&pPe, g_P_enc);
    cudaGetSymbolAddress((void**)&pPd, g_P_dec);
    cudaGetSymbolAddress((void**)&pEnc, g_enc_out);
    cudaGetSymbolAddress((void**)&pHf, g_h_final);
    cudaGetSymbolAddress((void**)&pHd, g_Hdec);
    cudaGetSymbolAddress((void**)&pComb, g_comb);
    cudaGetSymbolAddress((void**)&pAo, g_attn_out);

    // 1. transpose recurrent weights (coalesced-friendly layout for the RNN kernels)
    k_transpose<<<H_, H_>>>(W_hh_enc, pWTe);
    k_transpose<<<H_, H_>>>(W_hh_dec, pWTd);

    // 2. batched input projections (embedding gather fused into GEMM)
    k_gemm<64, 64, 16, 4, 4><<<dim3(H_ / 64, (B_ * S_) / 64), 256>>>(
        B_ * S_, H_, E_, emb_enc, indices_de, W_ih_enc, pPe, b_ih_enc, b_hh_enc, 0);
    k_gemm<64, 64, 16, 4, 4><<<dim3(H_ / 64, (B_ * T_) / 64), 256>>>(
        B_ * T_, H_, E_, emb_dec, indices_en, W_ih_dec, pPd, b_ih_dec, b_hh_dec, 0);

    // 3. sequential recurrences (only truly serial part)
    k_rnn<<<B_, H_>>>(pPe, pWTe, lengths_de, nullptr, pEnc, pHf, nullptr, S_);
    k_rnn<<<B_, H_>>>(pPd, pWTd, nullptr, pHf, pHd, nullptr, pComb, T_);

    // 4. attention over all (b,t) in parallel -> context into comb[:, 0:H]
    k_attn<<<dim3(B_, T_ / 16), 256>>>(pHd, pEnc, indices_de, pComb);

    // 5. attn_out = tanh([context|h] @ W_attn^T + b_attn)
    k_gemm<64, 64, 16, 4, 4><<<dim3(H_ / 64, (B_ * T_) / 64), 256>>>(
        B_ * T_, H_, 2 * H_, pComb, nullptr, W_attn, pAo, b_attn, nullptr, 1);

    // 6. logits = attn_out @ W_out^T + b_out  (dominant GEMM, [4096,256]x[256,32000])
    k_gemm<128, 128, 16, 8, 8><<<dim3(V_ / 128, (B_ * T_) / 128), 256>>>(
        B_ * T_, V_, H_, pAo, nullptr, W_out, out, b_out, nullptr, 0);
}

// round 5
// speedup vs baseline: 1.3741x; 1.3741x over previous
#include <cuda_runtime.h>
#include <cuda_bf16.h>
#include <cstdint>
#include <cstddef>

#define B_ 32
#define S_ 128
#define T_ 128
#define V_ 32000
#define E_ 256
#define H_ 256
#define NEGV -1.0e9f

// ================= scratch (static device memory; no allocation) =================
__device__ float g_WhhT_enc[H_ * H_];
__device__ float g_WhhT_dec[H_ * H_];
__device__ float g_P_enc[B_ * S_ * H_];
__device__ float g_P_dec[B_ * T_ * H_];
__device__ float g_enc_out[B_ * S_ * H_];
__device__ float g_h_final[B_ * H_];
__device__ float g_Hdec[B_ * T_ * H_];
__device__ float g_comb[B_ * T_ * 2 * H_];
__device__ float g_attn_out[B_ * T_ * H_];
__device__ __nv_bfloat16 g_W_hi[V_ * H_];
__device__ __nv_bfloat16 g_W_lo[V_ * H_];
__device__ __nv_bfloat16 g_A_hi[B_ * T_ * H_];
__device__ __nv_bfloat16 g_A_lo[B_ * T_ * H_];

// ================= PTX helpers (sm_80-compatible only; no 'a' features) =================
__device__ __forceinline__ uint32_t smem_u32(const void* p) {
    uint32_t a;
    asm("{ .reg .u64 t; cvta.to.shared.u64 t, %1; cvt.u32.u64 %0, t; }" : "=r"(a) : "l"(p));
    return a;
}
#define CP_ASYNC16(saddr, gaddr) \
    asm volatile("cp.async.cg.shared.global [%0], [%1], 16;" :: "r"(saddr), "l"(gaddr))
#define CP_COMMIT() asm volatile("cp.async.commit_group;")
#define CP_WAIT0()  asm volatile("cp.async.wait_group 0;")
#define LDSM_X4(r, addr) \
    asm volatile("ldmatrix.sync.aligned.m8n8.x4.shared.b16 {%0,%1,%2,%3}, [%4];" \
        : "=r"((r)[0]), "=r"((r)[1]), "=r"((r)[2]), "=r"((r)[3]) : "r"(addr))
#define MMA16816(d, a, b) \
    asm volatile("mma.sync.aligned.m16n8k16.row.col.f32.bf16.bf16.f32 " \
        "{%0,%1,%2,%3}, {%4,%5,%6,%7}, {%8,%9}, {%0,%1,%2,%3};" \
        : "+f"((d)[0]), "+f"((d)[1]), "+f"((d)[2]), "+f"((d)[3]) \
        : "r"((a)[0]), "r"((a)[1]), "r"((a)[2]), "r"((a)[3]), "r"((b)[0]), "r"((b)[1]))

// ================= fp32 -> bf16 hi/lo split (vector of 4) =================
__global__ void k_split4(const float4* __restrict__ x, __nv_bfloat16* __restrict__ hi,
                         __nv_bfloat16* __restrict__ lo) {
    int i = blockIdx.x * blockDim.x + threadIdx.x;
    float4 v = x[i];
    __nv_bfloat16 h0 = __float2bfloat16(v.x), h1 = __float2bfloat16(v.y);
    __nv_bfloat16 h2 = __float2bfloat16(v.z), h3 = __float2bfloat16(v.w);
    __nv_bfloat16 l0 = __float2bfloat16(v.x - __bfloat162float(h0));
    __nv_bfloat16 l1 = __float2bfloat16(v.y - __bfloat162float(h1));
    __nv_bfloat16 l2 = __float2bfloat16(v.z - __bfloat162float(h2));
    __nv_bfloat16 l3 = __float2bfloat16(v.w - __bfloat162float(h3));
    __nv_bfloat162* H = (__nv_bfloat162*)(hi + (size_t)i * 4);
    __nv_bfloat162* L = (__nv_bfloat162*)(lo + (size_t)i * 4);
    H[0] = __halves2bfloat162(h0, h1); H[1] = __halves2bfloat162(h2, h3);
    L[0] = __halves2bfloat162(l0, l1); L[1] = __halves2bfloat162(l2, l3);
}

// ================= mma.sync bf16x3 logits GEMM =================
// C[4096,32000] = Ahi@Whi^T + Ahi@Wlo^T + Alo@Whi^T + bias ; fp32 accumulate.
// CTA tile 128x128, BK=64 (4 chunks over K=256), 8 warps in 4(m)x2(n), warp tile 32x64.
// smem row stride = 72 bf16 (144 B) -> conflict-free ldmatrix phases.
#define LG_STRIDE 144                     // bytes per smem row (72 bf16)
#define LG_MAT (128 * LG_STRIDE)          // 18432 B per matrix tile
#define LG_AHI 0
#define LG_ALO (LG_MAT)
#define LG_WHI (2 * LG_MAT)
#define LG_WLO (3 * LG_MAT)
#define LG_BUF (4 * LG_MAT)               // 73728 B per buffer
#define SMEM_LOGITS (2 * LG_BUF)          // 147456 B

__device__ __forceinline__ void lg_load(
    uint32_t sb, const __nv_bfloat16* __restrict__ Ahi, const __nv_bfloat16* __restrict__ Alo,
    const __nv_bfloat16* __restrict__ Whi, const __nv_bfloat16* __restrict__ Wlo,
    int m0, int n0, int kc, int tid) {
#pragma unroll
    for (int i = 0; i < 4; i++) {
        int idx = tid + i * 256;          // 0..1023
        int r = idx >> 3, c = idx & 7;
        uint32_t soff = r * LG_STRIDE + c * 16;
        size_t ga = (size_t)(m0 + r) * H_ + kc * 64 + c * 8;
        size_t gw = (size_t)(n0 + r) * H_ + kc * 64 + c * 8;
        CP_ASYNC16(sb + LG_AHI + soff, Ahi + ga);
        CP_ASYNC16(sb + LG_ALO + soff, Alo + ga);
        CP_ASYNC16(sb + LG_WHI + soff, Whi + gw);
        CP_ASYNC16(sb + LG_WLO + soff, Wlo + gw);
    }
}

__global__ __launch_bounds__(256) void k_logits_mma(
    const __nv_bfloat16* __restrict__ Ahi, const __nv_bfloat16* __restrict__ Alo,
    const __nv_bfloat16* __restrict__ Whi, const __nv_bfloat16* __restrict__ Wlo,
    const float* __restrict__ bias, float* __restrict__ out) {
    extern __shared__ char smem[];
    const uint32_t sbase = smem_u32(smem);
    const int tid = threadIdx.x, wid = tid >> 5, lane = tid & 31;
    const int warp_m = wid & 3, warp_n = wid >> 2;
    const int m0 = blockIdx.y * 128;
    const int n0 = blockIdx.x * 128;

    float acc[2][8][4];
#pragma unroll
    for (int mt = 0; mt < 2; mt++)
#pragma unroll
        for (int nt = 0; nt < 8; nt++)
#pragma unroll
            for (int q = 0; q < 4; q++) acc[mt][nt][q] = 0.0f;

    lg_load(sbase, Ahi, Alo, Whi, Wlo, m0, n0, 0, tid);
    CP_COMMIT();
    CP_WAIT0();
    __syncthreads();

    // ldmatrix lane addressing (byte offsets within a tile)
    const int g = lane >> 3, r8 = lane & 7;
    // A: matrices {rows0-7 k0, rows8-15 k0, rows0-7 k8, rows8-15 k8}
    const uint32_t a_off = (uint32_t)(warp_m * 32 + (g & 1) * 8 + r8) * LG_STRIDE +
                           (uint32_t)((g >> 1) * 8) * 2;
    // B: matrices {nt2p k0, nt2p k8, nt2p+1 k0, nt2p+1 k8}
    const uint32_t b_off = (uint32_t)(warp_n * 64 + (g >> 1) * 8 + r8) * LG_STRIDE +
                           (uint32_t)((g & 1) * 8) * 2;

    for (int kc = 0; kc < 4; kc++) {
        const uint32_t buf = sbase + (kc & 1) * LG_BUF;
        if (kc < 3) {
            lg_load(sbase + ((kc + 1) & 1) * LG_BUF, Ahi, Alo, Whi, Wlo, m0, n0, kc + 1, tid);
            CP_COMMIT();
        }
#pragma unroll
        for (int ks = 0; ks < 4; ks++) {
            const uint32_t koff = (uint32_t)(ks * 16) * 2;
            uint32_t af[2][4], bf[8][2];
            // --- A hi, W hi ---
#pragma unroll
            for (int mt = 0; mt < 2; mt++)
                LDSM_X4(af[mt], buf + LG_AHI + a_off + mt * (16 * LG_STRIDE) + koff);
#pragma unroll
            for (int p = 0; p < 4; p++) {
                uint32_t t[4];
                LDSM_X4(t, buf + LG_WHI + b_off + p * (16 * LG_STRIDE) + koff);
                bf[2 * p][0] = t[0]; bf[2 * p][1] = t[1];
                bf[2 * p + 1][0] = t[2]; bf[2 * p + 1][1] = t[3];
            }
#pragma unroll
            for (int mt = 0; mt < 2; mt++)
#pragma unroll
                for (int nt = 0; nt < 8; nt++) MMA16816(acc[mt][nt], af[mt], bf[nt]);
            // --- A lo x W hi (reuse bf) ---
            uint32_t al[2][4];
#pragma unroll
            for (int mt = 0; mt < 2; mt++)
                LDSM_X4(al[mt], buf + LG_ALO + a_off + mt * (16 * LG_STRIDE) + koff);
#pragma unroll
            for (int mt = 0; mt < 2; mt++)
#pragma unroll
                for (int nt = 0; nt < 8; nt++) MMA16816(acc[mt][nt], al[mt], bf[nt]);
            // --- A hi x W lo (reuse af, overwrite bf) ---
#pragma unroll
            for (int p = 0; p < 4; p++) {
                uint32_t t[4];
                LDSM_X4(t, buf + LG_WLO + b_off + p * (16 * LG_STRIDE) + koff);
                bf[2 * p][0] = t[0]; bf[2 * p][1] = t[1];
                bf[2 * p + 1][0] = t[2]; bf[2 * p + 1][1] = t[3];
            }
#pragma unroll
            for (int mt = 0; mt < 2; mt++)
#pragma unroll
                for (int nt = 0; nt < 8; nt++) MMA16816(acc[mt][nt], af[mt], bf[nt]);
        }
        if (kc < 3) {
            CP_WAIT0();
            __syncthreads();
        }
    }

    // epilogue: c0,c1 -> (row l/4, col 2(l%4)); c2,c3 -> row+8
    const int er = lane >> 2, ec = (lane & 3) * 2;
#pragma unroll
    for (int mt = 0; mt < 2; mt++) {
        const int row0 = m0 + warp_m * 32 + mt * 16 + er;
#pragma unroll
        for (int nt = 0; nt < 8; nt++) {
            const int col0 = n0 + warp_n * 64 + nt * 8 + ec;
            float2 bb = *(const float2*)(bias + col0);
            float2 o0, o1;
            o0.x = acc[mt][nt][0] + bb.x; o0.y = acc[mt][nt][1] + bb.y;
            o1.x = acc[mt][nt][2] + bb.x; o1.y = acc[mt][nt][3] + bb.y;
            *(float2*)(out + (size_t)row0 * V_ + col0) = o0;
            *(float2*)(out + (size_t)(row0 + 8) * V_ + col0) = o1;
        }
    }
}

// ================= tiny transpose: out[k][j] = in[j][k], 256x256 =================
__global__ void k_transpose(const float* __restrict__ in, float* __restrict__ out) {
    int r = blockIdx.x, c = threadIdx.x;
    out[c * H_ + r] = in[r * H_ + c];
}

// ================= generic fp32 SIMT GEMM (small ops only) =================
template <int BM, int BN, int BK, int TM, int TN>
__global__ __launch_bounds__(256) void k_gemm(
    int M, int N, int K,
    const float* __restrict__ A, const int* __restrict__ gidx,
    const float* __restrict__ Bm, float* __restrict__ C,
    const float* __restrict__ bias1, const float* __restrict__ bias2, int act) {
    constexpr int KV = BK / 4;
    constexpr int RPP = 256 / KV;
    constexpr int AP = BM / RPP;
    constexpr int BP = BN / RPP;

    __shared__ __align__(16) float As[2][BK][BM];
    __shared__ __align__(16) float Bs[2][BK][BN];

    const int tid = threadIdx.x;
    const int m0 = blockIdx.y * BM;
    const int n0 = blockIdx.x * BN;
    const int lr = tid / KV;
    const int lk = tid % KV;

    const float* ap[AP];
    const float* bp[BP];
#pragma unroll
    for (int p = 0; p < AP; p++) {
        int gm = m0 + lr + p * RPP;
        int grow = gidx ? gidx[gm] : gm;
        ap[p] = A + (size_t)grow * K + lk * 4;
    }
#pragma unroll
    for (int p = 0; p < BP; p++)
        bp[p] = Bm + (size_t)(n0 + lr + p * RPP) * K + lk * 4;

    float acc[TM][TN];
#pragma unroll
    for (int i = 0; i < TM; i++)
#pragma unroll
        for (int j = 0; j < TN; j++) acc[i][j] = 0.0f;

    float4 ar[AP], br[BP];
#pragma unroll
    for (int p = 0; p < AP; p++) ar[p] = *(const float4*)(ap[p]);
#pragma unroll
    for (int p = 0; p < BP; p++) br[p] = *(const float4*)(bp[p]);
#pragma unroll
    for (int p = 0; p < AP; p++) {
        int m = lr + p * RPP;
        As[0][lk * 4 + 0][m] = ar[p].x; As[0][lk * 4 + 1][m] = ar[p].y;
        As[0][lk * 4 + 2][m] = ar[p].z; As[0][lk * 4 + 3][m] = ar[p].w;
    }
#pragma unroll
    for (int p = 0; p < BP; p++) {
        int n = lr + p * RPP;
        Bs[0][lk * 4 + 0][n] = br[p].x; Bs[0][lk * 4 + 1][n] = br[p].y;
        Bs[0][lk * 4 + 2][n] = br[p].z; Bs[0][lk * 4 + 3][n] = br[p].w;
    }
    __syncthreads();

    const int NT = K / BK;
    const int trow = tid / (BN / TN);
    const int tcol = tid % (BN / TN);

    for (int kt = 0; kt < NT; kt++) {
        const int cur = kt & 1;
        if (kt + 1 < NT) {
#pragma unroll
            for (int p = 0; p < AP; p++) ar[p] = *(const float4*)(ap[p] + (kt + 1) * BK);
#pragma unroll
            for (int p = 0; p < BP; p++) br[p] = *(const float4*)(bp[p] + (kt + 1) * BK);
        }
#pragma unroll
        for (int k = 0; k < BK; k++) {
            float a[TM], bf[TN];
#pragma unroll
            for (int i = 0; i < TM; i += 4) {
                float4 v = *(const float4*)&As[cur][k][trow * TM + i];
                a[i] = v.x; a[i + 1] = v.y; a[i + 2] = v.z; a[i + 3] = v.w;
            }
#pragma unroll
            for (int j = 0; j < TN; j += 4) {
                float4 v = *(const float4*)&Bs[cur][k][tcol * TN + j];
                bf[j] = v.x; bf[j + 1] = v.y; bf[j + 2] = v.z; bf[j + 3] = v.w;
            }
#pragma unroll
            for (int i = 0; i < TM; i++)
#pragma unroll
                for (int j = 0; j < TN; j++) acc[i][j] += a[i] * bf[j];
        }
        if (kt + 1 < NT) {
            const int nxt = cur ^ 1;
#pragma unroll
            for (int p = 0; p < AP; p++) {
                int m = lr + p * RPP;
                As[nxt][lk * 4 + 0][m] = ar[p].x; As[nxt][lk * 4 + 1][m] = ar[p].y;
                As[nxt][lk * 4 + 2][m] = ar[p].z; As[nxt][lk * 4 + 3][m] = ar[p].w;
            }
#pragma unroll
            for (int p = 0; p < BP; p++) {
                int n = lr + p * RPP;
                Bs[nxt][lk * 4 + 0][n] = br[p].x; Bs[nxt][lk * 4 + 1][n] = br[p].y;
                Bs[nxt][lk * 4 + 2][n] = br[p].z; Bs[nxt][lk * 4 + 3][n] = br[p].w;
            }
            __syncthreads();
        }
    }

    float bv[TN];
#pragma unroll
    for (int j = 0; j < TN; j++) {
        int n = n0 + tcol * TN + j;
        float v = bias1 ? bias1[n] : 0.0f;
        if (bias2) v += bias2[n];
        bv[j] = v;
    }
#pragma unroll
    for (int i = 0; i < TM; i++) {
        int m = m0 + trow * TM + i;
        float* crow = C + (size_t)m * N + n0 + tcol * TN;
#pragma unroll
        for (int j = 0; j < TN; j += 4) {
            float4 o;
            o.x = acc[i][j + 0] + bv[j + 0];
            o.y = acc[i][j + 1] + bv[j + 1];
            o.z = acc[i][j + 2] + bv[j + 2];
            o.w = acc[i][j + 3] + bv[j + 3];
            if (act) { o.x = tanhf(o.x); o.y = tanhf(o.y); o.z = tanhf(o.z); o.w = tanhf(o.w); }
            *(float4*)(crow + j) = o;
        }
    }
}

// ================= RNN recurrence: one CTA per batch element =================
__global__ __launch_bounds__(256) void k_rnn(
    const float* __restrict__ P, const float* __restrict__ WT,
    const int* __restrict__ lengths, const float* __restrict__ h0,
    float* __restrict__ outSeq, float* __restrict__ hFin,
    float* __restrict__ combHalf, int steps) {
    const int b = blockIdx.x;
    const int j = threadIdx.x;
    __shared__ __align__(16) float hs[H_];
    hs[j] = h0 ? h0[b * H_ + j] : 0.0f;
    __syncthreads();
    const int len = lengths ? lengths[b] : steps;
    const float* Pb = P + (size_t)b * steps * H_;
    float* Ob = outSeq + (size_t)b * steps * H_;
    const float* w = WT + j;

    for (int t = 0; t < steps; t++) {
        float a0 = 0.f, a1 = 0.f, a2 = 0.f, a3 = 0.f;
#pragma unroll 8
        for (int k = 0; k < H_; k += 4) {
            float4 h4 = *(const float4*)&hs[k];
            a0 += h4.x * w[(k + 0) * H_];
            a1 += h4.y * w[(k + 1) * H_];
            a2 += h4.z * w[(k + 2) * H_];
            a3 += h4.w * w[(k + 3) * H_];
        }
        float hn = tanhf(Pb[t * H_ + j] + ((a0 + a1) + (a2 + a3)));
        bool valid = t < len;
        __syncthreads();
        if (valid) hs[j] = hn;
        Ob[t * H_ + j] = valid ? hn : 0.0f;
        if (combHalf)
            combHalf[((size_t)(b * steps + t)) * (2 * H_) + H_ + j] = hn;
        __syncthreads();
    }
    if (hFin) hFin[b * H_ + j] = hs[j];
}

// ================= fused attention: scores -> softmax -> context =================
__global__ __launch_bounds__(256) void k_attn(
    const float* __restrict__ Hdec, const float* __restrict__ enc,
    const int* __restrict__ idx_de, float* __restrict__ comb) {
    const int b = blockIdx.x;
    const int t0 = blockIdx.y * 16;
    const int tid = threadIdx.x;
    __shared__ __align__(16) float hs[16][H_];
    __shared__ float sc[16][132];
    __shared__ int msk[S_];

    const float4* Hb4 = (const float4*)(Hdec + ((size_t)b * T_ + t0) * H_);
#pragma unroll
    for (int i = 0; i < 4; i++)
        ((float4*)hs)[tid + i * 256] = Hb4[tid + i * 256];
    if (tid < S_) msk[tid] = idx_de[b * S_ + tid];
    __syncthreads();

    const float* Eb = enc + (size_t)b * S_ * H_;
    {
        const int ti = tid >> 4, sg = tid & 15;
        const float4* h4 = (const float4*)hs[ti];
        for (int r = 0; r < 8; r++) {
            int s = r * 16 + sg;
            const float4* e4 = (const float4*)(Eb + s * H_);
            float a0 = 0.f, a1 = 0.f, a2 = 0.f, a3 = 0.f;
#pragma unroll 8
            for (int k = 0; k < H_ / 4; k++) {
                float4 e = e4[k], h = h4[k];
                a0 += e.x * h.x; a1 += e.y * h.y;
                a2 += e.z * h.z; a3 += e.w * h.w;
            }
            sc[ti][s] = (msk[s] == 0) ? NEGV : ((a0 + a1) + (a2 + a3));
        }
    }
    __syncthreads();
    {
        const int w = tid >> 5, lane = tid & 31;
#pragma unroll
        for (int rr = 0; rr < 2; rr++) {
            int row = w * 2 + rr;
            float v0 = sc[row][lane], v1 = sc[row][lane + 32];
            float v2 = sc[row][lane + 64], v3 = sc[row][lane + 96];
            float m = fmaxf(fmaxf(v0, v1), fmaxf(v2, v3));
#pragma unroll
            for (int o = 16; o > 0; o >>= 1)
                m = fmaxf(m, __shfl_xor_sync(0xffffffffu, m, o));
            float e0 = expf(v0 - m), e1 = expf(v1 - m);
            float e2 = expf(v2 - m), e3 = expf(v3 - m);
            float sum = (e0 + e1) + (e2 + e3);
#pragma unroll
            for (int o = 16; o > 0; o >>= 1)
                sum += __shfl_xor_sync(0xffffffffu, sum, o);
            float inv = 1.0f / sum;
            sc[row][lane] = e0 * inv; sc[row][lane + 32] = e1 * inv;
            sc[row][lane + 64] = e2 * inv; sc[row][lane + 96] = e3 * inv;
        }
    }
    __syncthreads();
    {
        const int ti = tid & 15, jg = tid >> 4;
        float4 c0 = {0, 0, 0, 0}, c1 = c0, c2 = c0, c3 = c0;
        for (int s = 0; s < S_; s++) {
            float p = sc[ti][s];
            const float4* e4 = (const float4*)(Eb + s * H_ + jg * 16);
            float4 e0 = e4[0], e1 = e4[1], e2 = e4[2], e3 = e4[3];
            c0.x += p * e0.x; c0.y += p * e0.y; c0.z += p * e0.z; c0.w += p * e0.w;
            c1.x += p * e1.x; c1.y += p * e1.y; c1.z += p * e1.z; c1.w += p * e1.w;
            c2.x += p * e2.x; c2.y += p * e2.y; c2.z += p * e2.z; c2.w += p * e2.w;
            c3.x += p * e3.x; c3.y += p * e3.y; c3.z += p * e3.z; c3.w += p * e3.w;
        }
        float* dst = comb + ((size_t)(b * T_ + t0 + ti)) * (2 * H_) + jg * 16;
        ((float4*)dst)[0] = c0; ((float4*)dst)[1] = c1;
        ((float4*)dst)[2] = c2; ((float4*)dst)[3] = c3;
    }
}

// ================= launch =================
extern "C" void kernel_launch(void* const* d_in, const int* in_sizes, int n_in,
                              void* d_out, int out_size) {
    const int* indices_de = (const int*)d_in[0];
    const int* lengths_de = (const int*)d_in[1];
    const int* indices_en = (const int*)d_in[2];
    const float* emb_enc = (const float*)d_in[4];
    const float* emb_dec = (const float*)d_in[5];
    const float* W_ih_enc = (const float*)d_in[6];
    const float* W_hh_enc = (const float*)d_in[7];
    const float* b_ih_enc = (const float*)d_in[8];
    const float* b_hh_enc = (const float*)d_in[9];
    const float* W_ih_dec = (const float*)d_in[10];
    const float* W_hh_dec = (const float*)d_in[11];
    const float* b_ih_dec = (const float*)d_in[12];
    const float* b_hh_dec = (const float*)d_in[13];
    const float* W_attn = (const float*)d_in[14];
    const float* b_attn = (const float*)d_in[15];
    const float* W_out = (const float*)d_in[16];
    const float* b_out = (const float*)d_in[17];
    float* out = (float*)d_out;

    float *pWTe, *pWTd, *pPe, *pPd, *pEnc, *pHf, *pHd, *pComb, *pAo;
    __nv_bfloat16 *pWhi, *pWlo, *pAhi, *pAlo;
    cudaGetSymbolAddress((void**)&pWTe, g_WhhT_enc);
    cudaGetSymbolAddress((void**)&pWTd, g_WhhT_dec);
    cudaGetSymbolAddress((void**)&pPe, g_P_enc);
    cudaGetSymbolAddress((void**)&pPd, g_P_dec);
    cudaGetSymbolAddress((void**)&pEnc, g_enc_out);
    cudaGetSymbolAddress((void**)&pHf, g_h_final);
    cudaGetSymbolAddress((void**)&pHd, g_Hdec);
    cudaGetSymbolAddress((void**)&pComb, g_comb);
    cudaGetSymbolAddress((void**)&pAo, g_attn_out);
    cudaGetSymbolAddress((void**)&pWhi, g_W_hi);
    cudaGetSymbolAddress((void**)&pWlo, g_W_lo);
    cudaGetSymbolAddress((void**)&pAhi, g_A_hi);
    cudaGetSymbolAddress((void**)&pAlo, g_A_lo);

    cudaFuncSetAttribute(k_logits_mma, cudaFuncAttributeMaxDynamicSharedMemorySize,
                         SMEM_LOGITS);

    // 1. transpose recurrent weights; split W_out into bf16 hi/lo
    k_transpose<<<H_, H_>>>(W_hh_enc, pWTe);
    k_transpose<<<H_, H_>>>(W_hh_dec, pWTd);
    k_split4<<<(V_ * H_ / 4) / 256, 256>>>((const float4*)W_out, pWhi, pWlo);

    // 2. batched input projections (embedding gather fused into GEMM)
    k_gemm<64, 64, 16, 4, 4><<<dim3(H_ / 64, (B_ * S_) / 64), 256>>>(
        B_ * S_, H_, E_, emb_enc, indices_de, W_ih_enc, pPe, b_ih_enc, b_hh_enc, 0);
    k_gemm<64, 64, 16, 4, 4><<<dim3(H_ / 64, (B_ * T_) / 64), 256>>>(
        B_ * T_, H_, E_, emb_dec, indices_en, W_ih_dec, pPd, b_ih_dec, b_hh_dec, 0);

    // 3. sequential recurrences
    k_rnn<<<B_, H_>>>(pPe, pWTe, lengths_de, nullptr, pEnc, pHf, nullptr, S_);
    k_rnn<<<B_, H_>>>(pPd, pWTd, nullptr, pHf, pHd, nullptr, pComb, T_);

    // 4. attention -> context into comb[:, 0:H]
    k_attn<<<dim3(B_, T_ / 16), 256>>>(pHd, pEnc, indices_de, pComb);

    // 5. attn_out = tanh([context|h] @ W_attn^T + b_attn)
    k_gemm<64, 64, 16, 4, 4><<<dim3(H_ / 64, (B_ * T_) / 64), 256>>>(
        B_ * T_, H_, 2 * H_, pComb, nullptr, W_attn, pAo, b_attn, nullptr, 1);

    // 6. split attn_out into bf16 hi/lo, then mma.sync bf16x3 logits GEMM
    k_split4<<<(B_ * T_ * H_ / 4) / 256, 256>>>((const float4*)pAo, pAhi, pAlo);
    k_logits_mma<<<dim3(V_ / 128, (B_ * T_) / 128), 256, SMEM_LOGITS>>>(
        pAhi, pAlo, pWhi, pWlo, b_out, out);
}

// round 6
// speedup vs baseline: 1.5031x; 1.0939x over previous
#include <cuda_runtime.h>
#include <cuda_fp16.h>
#include <cstdint>
#include <cstddef>

#define B_ 32
#define S_ 128
#define T_ 128
#define V_ 32000
#define E_ 256
#define H_ 256
#define NEGV -1.0e9f

// ================= scratch (static device memory; no allocation) =================
__device__ float g_WhhT_enc[H_ * H_];
__device__ float g_WhhT_dec[H_ * H_];
__device__ float g_P_enc[B_ * S_ * H_];
__device__ float g_P_dec[B_ * T_ * H_];
__device__ float g_enc_out[B_ * S_ * H_];
__device__ float g_h_final[B_ * H_];
__device__ float g_Hdec[B_ * T_ * H_];
__device__ float g_comb[B_ * T_ * 2 * H_];
__device__ float g_attn_out[B_ * T_ * H_];
__device__ __half g_Wh[V_ * H_];           // W_out in fp16
__device__ __half g_A_hi[B_ * T_ * H_];    // attn_out fp16 hi
__device__ __half g_A_lo[B_ * T_ * H_];    // attn_out fp16 lo (residual)

// ================= PTX helpers (sm_80-compatible only; no 'a' features) =================
__device__ __forceinline__ uint32_t smem_u32(const void* p) {
    uint32_t a;
    asm("{ .reg .u64 t; cvta.to.shared.u64 t, %1; cvt.u32.u64 %0, t; }" : "=r"(a) : "l"(p));
    return a;
}
#define CP_ASYNC16(saddr, gaddr) \
    asm volatile("cp.async.cg.shared.global [%0], [%1], 16;" :: "r"(saddr), "l"(gaddr))
#define CP_COMMIT() asm volatile("cp.async.commit_group;")
#define CP_WAIT0()  asm volatile("cp.async.wait_group 0;")
#define LDSM_X4(r, addr) \
    asm volatile("ldmatrix.sync.aligned.m8n8.x4.shared.b16 {%0,%1,%2,%3}, [%4];" \
        : "=r"((r)[0]), "=r"((r)[1]), "=r"((r)[2]), "=r"((r)[3]) : "r"(addr))
#define MMA16816F16(d, a, b) \
    asm volatile("mma.sync.aligned.m16n8k16.row.col.f32.f16.f16.f32 " \
        "{%0,%1,%2,%3}, {%4,%5,%6,%7}, {%8,%9}, {%0,%1,%2,%3};" \
        : "+f"((d)[0]), "+f"((d)[1]), "+f"((d)[2]), "+f"((d)[3]) \
        : "r"((a)[0]), "r"((a)[1]), "r"((a)[2]), "r"((a)[3]), "r"((b)[0]), "r"((b)[1]))

// ================= fp32 -> fp16 hi/lo split (vector of 4) =================
__global__ void k_split4h(const float4* __restrict__ x, __half* __restrict__ hi,
                          __half* __restrict__ lo) {
    int i = blockIdx.x * blockDim.x + threadIdx.x;
    float4 v = x[i];
    __half h0 = __float2half_rn(v.x), h1 = __float2half_rn(v.y);
    __half h2 = __float2half_rn(v.z), h3 = __float2half_rn(v.w);
    __half l0 = __float2half_rn(v.x - __half2float(h0));
    __half l1 = __float2half_rn(v.y - __half2float(h1));
    __half l2 = __float2half_rn(v.z - __half2float(h2));
    __half l3 = __float2half_rn(v.w - __half2float(h3));
    __half2* H = (__half2*)(hi + (size_t)i * 4);
    __half2* L = (__half2*)(lo + (size_t)i * 4);
    H[0] = __halves2half2(h0, h1); H[1] = __halves2half2(h2, h3);
    L[0] = __halves2half2(l0, l1); L[1] = __halves2half2(l2, l3);
}

// ================= fp32 -> fp16 convert (vector of 4) =================
__global__ void k_cvt4h(const float4* __restrict__ x, __half* __restrict__ o) {
    int i = blockIdx.x * blockDim.x + threadIdx.x;
    float4 v = x[i];
    __half2* O = (__half2*)(o + (size_t)i * 4);
    O[0] = __halves2half2(__float2half_rn(v.x), __float2half_rn(v.y));
    O[1] = __halves2half2(__float2half_rn(v.z), __float2half_rn(v.w));
}

// ================= mma.sync fp16x2 logits GEMM =================
// C[4096,32000] = Ahi@Wh^T + Alo@Wh^T + bias ; fp32 accumulate.
// CTA tile 128x128, BK=64 (4 chunks over K=256), 8 warps in 4(m)x2(n), warp tile 32x64.
// smem row stride = 144 B (64 fp16 + 8 pad) -> conflict-free ldmatrix phases.
#define LG_STRIDE 144
#define LG_MAT (128 * LG_STRIDE)          // 18432 B per matrix tile
#define LG_AHI 0
#define LG_ALO (LG_MAT)
#define LG_W   (2 * LG_MAT)
#define LG_BUF (3 * LG_MAT)               // 55296 B per buffer
#define SMEM_LOGITS (2 * LG_BUF)          // 110592 B -> 2 CTAs/SM

__device__ __forceinline__ void lg_load(
    uint32_t sb, const __half* __restrict__ Ahi, const __half* __restrict__ Alo,
    const __half* __restrict__ Wh, int m0, int n0, int kc, int tid) {
#pragma unroll
    for (int i = 0; i < 4; i++) {
        int idx = tid + i * 256;          // 0..1023
        int r = idx >> 3, c = idx & 7;
        uint32_t soff = r * LG_STRIDE + c * 16;
        size_t ga = (size_t)(m0 + r) * H_ + kc * 64 + c * 8;
        size_t gw = (size_t)(n0 + r) * H_ + kc * 64 + c * 8;
        CP_ASYNC16(sb + LG_AHI + soff, Ahi + ga);
        CP_ASYNC16(sb + LG_ALO + soff, Alo + ga);
        CP_ASYNC16(sb + LG_W + soff, Wh + gw);
    }
}

__global__ __launch_bounds__(256, 2) void k_logits_mma(
    const __half* __restrict__ Ahi, const __half* __restrict__ Alo,
    const __half* __restrict__ Wh,
    const float* __restrict__ bias, float* __restrict__ out) {
    extern __shared__ char smem[];
    const uint32_t sbase = smem_u32(smem);
    const int tid = threadIdx.x, wid = tid >> 5, lane = tid & 31;
    const int warp_m = wid & 3, warp_n = wid >> 2;
    const int m0 = blockIdx.x * 128;      // M on x: consecutive CTAs share W tile
    const int n0 = blockIdx.y * 128;

    float acc[2][8][4];
#pragma unroll
    for (int mt = 0; mt < 2; mt++)
#pragma unroll
        for (int nt = 0; nt < 8; nt++)
#pragma unroll
            for (int q = 0; q < 4; q++) acc[mt][nt][q] = 0.0f;

    lg_load(sbase, Ahi, Alo, Wh, m0, n0, 0, tid);
    CP_COMMIT();
    CP_WAIT0();
    __syncthreads();

    // ldmatrix lane addressing (byte offsets within a tile)
    const int g = lane >> 3, r8 = lane & 7;
    const uint32_t a_off = (uint32_t)(warp_m * 32 + (g & 1) * 8 + r8) * LG_STRIDE +
                           (uint32_t)((g >> 1) * 8) * 2;
    const uint32_t b_off = (uint32_t)(warp_n * 64 + (g >> 1) * 8 + r8) * LG_STRIDE +
                           (uint32_t)((g & 1) * 8) * 2;

    for (int kc = 0; kc < 4; kc++) {
        const uint32_t buf = sbase + (kc & 1) * LG_BUF;
        if (kc < 3) {
            lg_load(sbase + ((kc + 1) & 1) * LG_BUF, Ahi, Alo, Wh, m0, n0, kc + 1, tid);
            CP_COMMIT();
        }
#pragma unroll
        for (int ks = 0; ks < 4; ks++) {
            const uint32_t koff = (uint32_t)(ks * 16) * 2;
            uint32_t af[2][4], bf[8][2];
            // --- W tile (shared by both products) ---
#pragma unroll
            for (int p = 0; p < 4; p++) {
                uint32_t t[4];
                LDSM_X4(t, buf + LG_W + b_off + p * (16 * LG_STRIDE) + koff);
                bf[2 * p][0] = t[0]; bf[2 * p][1] = t[1];
                bf[2 * p + 1][0] = t[2]; bf[2 * p + 1][1] = t[3];
            }
            // --- A hi x W ---
#pragma unroll
            for (int mt = 0; mt < 2; mt++)
                LDSM_X4(af[mt], buf + LG_AHI + a_off + mt * (16 * LG_STRIDE) + koff);
#pragma unroll
            for (int mt = 0; mt < 2; mt++)
#pragma unroll
                for (int nt = 0; nt < 8; nt++) MMA16816F16(acc[mt][nt], af[mt], bf[nt]);
            // --- A lo x W (reuse bf) ---
#pragma unroll
            for (int mt = 0; mt < 2; mt++)
                LDSM_X4(af[mt], buf + LG_ALO + a_off + mt * (16 * LG_STRIDE) + koff);
#pragma unroll
            for (int mt = 0; mt < 2; mt++)
#pragma unroll
                for (int nt = 0; nt < 8; nt++) MMA16816F16(acc[mt][nt], af[mt], bf[nt]);
        }
        if (kc < 3) {
            CP_WAIT0();
            __syncthreads();
        }
    }

    // epilogue: c0,c1 -> (row l/4, col 2(l%4)); c2,c3 -> row+8
    const int er = lane >> 2, ec = (lane & 3) * 2;
#pragma unroll
    for (int mt = 0; mt < 2; mt++) {
        const int row0 = m0 + warp_m * 32 + mt * 16 + er;
#pragma unroll
        for (int nt = 0; nt < 8; nt++) {
            const int col0 = n0 + warp_n * 64 + nt * 8 + ec;
            float2 bb = *(const float2*)(bias + col0);
            float2 o0, o1;
            o0.x = acc[mt][nt][0] + bb.x; o0.y = acc[mt][nt][1] + bb.y;
            o1.x = acc[mt][nt][2] + bb.x; o1.y = acc[mt][nt][3] + bb.y;
            *(float2*)(out + (size_t)row0 * V_ + col0) = o0;
            *(float2*)(out + (size_t)(row0 + 8) * V_ + col0) = o1;
        }
    }
}

// ================= tiny transpose: out[k][j] = in[j][k], 256x256 =================
__global__ void k_transpose(const float* __restrict__ in, float* __restrict__ out) {
    int r = blockIdx.x, c = threadIdx.x;
    out[c * H_ + r] = in[r * H_ + c];
}

// ================= generic fp32 SIMT GEMM (small ops only) =================
template <int BM, int BN, int BK, int TM, int TN>
__global__ __launch_bounds__(256) void k_gemm(
    int M, int N, int K,
    const float* __restrict__ A, const int* __restrict__ gidx,
    const float* __restrict__ Bm, float* __restrict__ C,
    const float* __restrict__ bias1, const float* __restrict__ bias2, int act) {
    constexpr int KV = BK / 4;
    constexpr int RPP = 256 / KV;
    constexpr int AP = BM / RPP;
    constexpr int BP = BN / RPP;

    __shared__ __align__(16) float As[2][BK][BM];
    __shared__ __align__(16) float Bs[2][BK][BN];

    const int tid = threadIdx.x;
    const int m0 = blockIdx.y * BM;
    const int n0 = blockIdx.x * BN;
    const int lr = tid / KV;
    const int lk = tid % KV;

    const float* ap[AP];
    const float* bp[BP];
#pragma unroll
    for (int p = 0; p < AP; p++) {
        int gm = m0 + lr + p * RPP;
        int grow = gidx ? gidx[gm] : gm;
        ap[p] = A + (size_t)grow * K + lk * 4;
    }
#pragma unroll
    for (int p = 0; p < BP; p++)
        bp[p] = Bm + (size_t)(n0 + lr + p * RPP) * K + lk * 4;

    float acc[TM][TN];
#pragma unroll
    for (int i = 0; i < TM; i++)
#pragma unroll
        for (int j = 0; j < TN; j++) acc[i][j] = 0.0f;

    float4 ar[AP], br[BP];
#pragma unroll
    for (int p = 0; p < AP; p++) ar[p] = *(const float4*)(ap[p]);
#pragma unroll
    for (int p = 0; p < BP; p++) br[p] = *(const float4*)(bp[p]);
#pragma unroll
    for (int p = 0; p < AP; p++) {
        int m = lr + p * RPP;
        As[0][lk * 4 + 0][m] = ar[p].x; As[0][lk * 4 + 1][m] = ar[p].y;
        As[0][lk * 4 + 2][m] = ar[p].z; As[0][lk * 4 + 3][m] = ar[p].w;
    }
#pragma unroll
    for (int p = 0; p < BP; p++) {
        int n = lr + p * RPP;
        Bs[0][lk * 4 + 0][n] = br[p].x; Bs[0][lk * 4 + 1][n] = br[p].y;
        Bs[0][lk * 4 + 2][n] = br[p].z; Bs[0][lk * 4 + 3][n] = br[p].w;
    }
    __syncthreads();

    const int NT = K / BK;
    const int trow = tid / (BN / TN);
    const int tcol = tid % (BN / TN);

    for (int kt = 0; kt < NT; kt++) {
        const int cur = kt & 1;
        if (kt + 1 < NT) {
#pragma unroll
            for (int p = 0; p < AP; p++) ar[p] = *(const float4*)(ap[p] + (kt + 1) * BK);
#pragma unroll
            for (int p = 0; p < BP; p++) br[p] = *(const float4*)(bp[p] + (kt + 1) * BK);
        }
#pragma unroll
        for (int k = 0; k < BK; k++) {
            float a[TM], bf[TN];
#pragma unroll
            for (int i = 0; i < TM; i += 4) {
                float4 v = *(const float4*)&As[cur][k][trow * TM + i];
                a[i] = v.x; a[i + 1] = v.y; a[i + 2] = v.z; a[i + 3] = v.w;
            }
#pragma unroll
            for (int j = 0; j < TN; j += 4) {
                float4 v = *(const float4*)&Bs[cur][k][tcol * TN + j];
                bf[j] = v.x; bf[j + 1] = v.y; bf[j + 2] = v.z; bf[j + 3] = v.w;
            }
#pragma unroll
            for (int i = 0; i < TM; i++)
#pragma unroll
                for (int j = 0; j < TN; j++) acc[i][j] += a[i] * bf[j];
        }
        if (kt + 1 < NT) {
            const int nxt = cur ^ 1;
#pragma unroll
            for (int p = 0; p < AP; p++) {
                int m = lr + p * RPP;
                As[nxt][lk * 4 + 0][m] = ar[p].x; As[nxt][lk * 4 + 1][m] = ar[p].y;
                As[nxt][lk * 4 + 2][m] = ar[p].z; As[nxt][lk * 4 + 3][m] = ar[p].w;
            }
#pragma unroll
            for (int p = 0; p < BP; p++) {
                int n = lr + p * RPP;
                Bs[nxt][lk * 4 + 0][n] = br[p].x; Bs[nxt][lk * 4 + 1][n] = br[p].y;
                Bs[nxt][lk * 4 + 2][n] = br[p].z; Bs[nxt][lk * 4 + 3][n] = br[p].w;
            }
            __syncthreads();
        }
    }

    float bv[TN];
#pragma unroll
    for (int j = 0; j < TN; j++) {
        int n = n0 + tcol * TN + j;
        float v = bias1 ? bias1[n] : 0.0f;
        if (bias2) v += bias2[n];
        bv[j] = v;
    }
#pragma unroll
    for (int i = 0; i < TM; i++) {
        int m = m0 + trow * TM + i;
        float* crow = C + (size_t)m * N + n0 + tcol * TN;
#pragma unroll
        for (int j = 0; j < TN; j += 4) {
            float4 o;
            o.x = acc[i][j + 0] + bv[j + 0];
            o.y = acc[i][j + 1] + bv[j + 1];
            o.z = acc[i][j + 2] + bv[j + 2];
            o.w = acc[i][j + 3] + bv[j + 3];
            if (act) { o.x = tanhf(o.x); o.y = tanhf(o.y); o.z = tanhf(o.z); o.w = tanhf(o.w); }
            *(float4*)(crow + j) = o;
        }
    }
}

// ================= RNN recurrence: one CTA per batch element =================
__global__ __launch_bounds__(256) void k_rnn(
    const float* __restrict__ P, const float* __restrict__ WT,
    const int* __restrict__ lengths, const float* __restrict__ h0,
    float* __restrict__ outSeq, float* __restrict__ hFin,
    float* __restrict__ combHalf, int steps) {
    const int b = blockIdx.x;
    const int j = threadIdx.x;
    __shared__ __align__(16) float hs[H_];
    hs[j] = h0 ? h0[b * H_ + j] : 0.0f;
    __syncthreads();
    const int len = lengths ? lengths[b] : steps;
    const float* Pb = P + (size_t)b * steps * H_;
    float* Ob = outSeq + (size_t)b * steps * H_;
    const float* w = WT + j;

    for (int t = 0; t < steps; t++) {
        float a0 = 0.f, a1 = 0.f, a2 = 0.f, a3 = 0.f;
#pragma unroll 8
        for (int k = 0; k < H_; k += 4) {
            float4 h4 = *(const float4*)&hs[k];
            a0 += h4.x * w[(k + 0) * H_];
            a1 += h4.y * w[(k + 1) * H_];
            a2 += h4.z * w[(k + 2) * H_];
            a3 += h4.w * w[(k + 3) * H_];
        }
        float hn = tanhf(Pb[t * H_ + j] + ((a0 + a1) + (a2 + a3)));
        bool valid = t < len;
        __syncthreads();
        if (valid) hs[j] = hn;
        Ob[t * H_ + j] = valid ? hn : 0.0f;
        if (combHalf)
            combHalf[((size_t)(b * steps + t)) * (2 * H_) + H_ + j] = hn;
        __syncthreads();
    }
    if (hFin) hFin[b * H_ + j] = hs[j];
}

// ================= fused attention: scores -> softmax -> context =================
__global__ __launch_bounds__(256) void k_attn(
    const float* __restrict__ Hdec, const float* __restrict__ enc,
    const int* __restrict__ idx_de, float* __restrict__ comb) {
    const int b = blockIdx.x;
    const int t0 = blockIdx.y * 16;
    const int tid = threadIdx.x;
    __shared__ __align__(16) float hs[16][H_];
    __shared__ float sc[16][132];
    __shared__ int msk[S_];

    const float4* Hb4 = (const float4*)(Hdec + ((size_t)b * T_ + t0) * H_);
#pragma unroll
    for (int i = 0; i < 4; i++)
        ((float4*)hs)[tid + i * 256] = Hb4[tid + i * 256];
    if (tid < S_) msk[tid] = idx_de[b * S_ + tid];
    __syncthreads();

    const float* Eb = enc + (size_t)b * S_ * H_;
    {
        const int ti = tid >> 4, sg = tid & 15;
        const float4* h4 = (const float4*)hs[ti];
        for (int r = 0; r < 8; r++) {
            int s = r * 16 + sg;
            const float4* e4 = (const float4*)(Eb + s * H_);
            float a0 = 0.f, a1 = 0.f, a2 = 0.f, a3 = 0.f;
#pragma unroll 8
            for (int k = 0; k < H_ / 4; k++) {
                float4 e = e4[k], h = h4[k];
                a0 += e.x * h.x; a1 += e.y * h.y;
                a2 += e.z * h.z; a3 += e.w * h.w;
            }
            sc[ti][s] = (msk[s] == 0) ? NEGV : ((a0 + a1) + (a2 + a3));
        }
    }
    __syncthreads();
    {
        const int w = tid >> 5, lane = tid & 31;
#pragma unroll
        for (int rr = 0; rr < 2; rr++) {
            int row = w * 2 + rr;
            float v0 = sc[row][lane], v1 = sc[row][lane + 32];
            float v2 = sc[row][lane + 64], v3 = sc[row][lane + 96];
            float m = fmaxf(fmaxf(v0, v1), fmaxf(v2, v3));
#pragma unroll
            for (int o = 16; o > 0; o >>= 1)
                m = fmaxf(m, __shfl_xor_sync(0xffffffffu, m, o));
            float e0 = expf(v0 - m), e1 = expf(v1 - m);
            float e2 = expf(v2 - m), e3 = expf(v3 - m);
            float sum = (e0 + e1) + (e2 + e3);
#pragma unroll
            for (int o = 16; o > 0; o >>= 1)
                sum += __shfl_xor_sync(0xffffffffu, sum, o);
            float inv = 1.0f / sum;
            sc[row][lane] = e0 * inv; sc[row][lane + 32] = e1 * inv;
            sc[row][lane + 64] = e2 * inv; sc[row][lane + 96] = e3 * inv;
        }
    }
    __syncthreads();
    {
        const int ti = tid & 15, jg = tid >> 4;
        float4 c0 = {0, 0, 0, 0}, c1 = c0, c2 = c0, c3 = c0;
        for (int s = 0; s < S_; s++) {
            float p = sc[ti][s];
            const float4* e4 = (const float4*)(Eb + s * H_ + jg * 16);
            float4 e0 = e4[0], e1 = e4[1], e2 = e4[2], e3 = e4[3];
            c0.x += p * e0.x; c0.y += p * e0.y; c0.z += p * e0.z; c0.w += p * e0.w;
            c1.x += p * e1.x; c1.y += p * e1.y; c1.z += p * e1.z; c1.w += p * e1.w;
            c2.x += p * e2.x; c2.y += p * e2.y; c2.z += p * e2.z; c2.w += p * e2.w;
            c3.x += p * e3.x; c3.y += p * e3.y; c3.z += p * e3.z; c3.w += p * e3.w;
        }
        float* dst = comb + ((size_t)(b * T_ + t0 + ti)) * (2 * H_) + jg * 16;
        ((float4*)dst)[0] = c0; ((float4*)dst)[1] = c1;
        ((float4*)dst)[2] = c2; ((float4*)dst)[3] = c3;
    }
}

// ================= launch =================
extern "C" void kernel_launch(void* const* d_in, const int* in_sizes, int n_in,
                              void* d_out, int out_size) {
    const int* indices_de = (const int*)d_in[0];
    const int* lengths_de = (const int*)d_in[1];
    const int* indices_en = (const int*)d_in[2];
    const float* emb_enc = (const float*)d_in[4];
    const float* emb_dec = (const float*)d_in[5];
    const float* W_ih_enc = (const float*)d_in[6];
    const float* W_hh_enc = (const float*)d_in[7];
    const float* b_ih_enc = (const float*)d_in[8];
    const float* b_hh_enc = (const float*)d_in[9];
    const float* W_ih_dec = (const float*)d_in[10];
    const float* W_hh_dec = (const float*)d_in[11];
    const float* b_ih_dec = (const float*)d_in[12];
    const float* b_hh_dec = (const float*)d_in[13];
    const float* W_attn = (const float*)d_in[14];
    const float* b_attn = (const float*)d_in[15];
    const float* W_out = (const float*)d_in[16];
    const float* b_out = (const float*)d_in[17];
    float* out = (float*)d_out;

    float *pWTe, *pWTd, *pPe, *pPd, *pEnc, *pHf, *pHd, *pComb, *pAo;
    __half *pWh, *pAhi, *pAlo;
    cudaGetSymbolAddress((void**)&pWTe, g_WhhT_enc);
    cudaGetSymbolAddress((void**)&pWTd, g_WhhT_dec);
    cudaGetSymbolAddress((void**)&pPe, g_P_enc);
    cudaGetSymbolAddress((void**)&pPd, g_P_dec);
    cudaGetSymbolAddress((void**)&pEnc, g_enc_out);
    cudaGetSymbolAddress((void**)&pHf, g_h_final);
    cudaGetSymbolAddress((void**)&pHd, g_Hdec);
    cudaGetSymbolAddress((void**)&pComb, g_comb);
    cudaGetSymbolAddress((void**)&pAo, g_attn_out);
    cudaGetSymbolAddress((void**)&pWh, g_Wh);
    cudaGetSymbolAddress((void**)&pAhi, g_A_hi);
    cudaGetSymbolAddress((void**)&pAlo, g_A_lo);

    cudaFuncSetAttribute(k_logits_mma, cudaFuncAttributeMaxDynamicSharedMemorySize,
                         SMEM_LOGITS);

    // 1. transpose recurrent weights; convert W_out to fp16
    k_transpose<<<H_, H_>>>(W_hh_enc, pWTe);
    k_transpose<<<H_, H_>>>(W_hh_dec, pWTd);
    k_cvt4h<<<(V_ * H_ / 4) / 256, 256>>>((const float4*)W_out, pWh);

    // 2. batched input projections (embedding gather fused into GEMM)
    k_gemm<64, 64, 16, 4, 4><<<dim3(H_ / 64, (B_ * S_) / 64), 256>>>(
        B_ * S_, H_, E_, emb_enc, indices_de, W_ih_enc, pPe, b_ih_enc, b_hh_enc, 0);
    k_gemm<64, 64, 16, 4, 4><<<dim3(H_ / 64, (B_ * T_) / 64), 256>>>(
        B_ * T_, H_, E_, emb_dec, indices_en, W_ih_dec, pPd, b_ih_dec, b_hh_dec, 0);

    // 3. sequential recurrences
    k_rnn<<<B_, H_>>>(pPe, pWTe, lengths_de, nullptr, pEnc, pHf, nullptr, S_);
    k_rnn<<<B_, H_>>>(pPd, pWTd, nullptr, pHf, pHd, nullptr, pComb, T_);

    // 4. attention -> context into comb[:, 0:H]
    k_attn<<<dim3(B_, T_ / 16), 256>>>(pHd, pEnc, indices_de, pComb);

    // 5. attn_out = tanh([context|h] @ W_attn^T + b_attn)
    k_gemm<64, 64, 16, 4, 4><<<dim3(H_ / 64, (B_ * T_) / 64), 256>>>(
        B_ * T_, H_, 2 * H_, pComb, nullptr, W_attn, pAo, b_attn, nullptr, 1);

    // 6. split attn_out into fp16 hi/lo, then mma.sync fp16x2 logits GEMM
    k_split4h<<<(B_ * T_ * H_ / 4) / 256, 256>>>((const float4*)pAo, pAhi, pAlo);
    k_logits_mma<<<dim3((B_ * T_) / 128, V_ / 128), 256, SMEM_LOGITS>>>(
        pAhi, pAlo, pWh, b_out, out);
}

// round 7
// speedup vs baseline: 3.6303x; 2.4152x over previous
#include <cuda_runtime.h>
#include <cuda_fp16.h>
#include <cstdint>
#include <cstddef>

#define B_ 32
#define S_ 128
#define T_ 128
#define V_ 32000
#define E_ 256
#define H_ 256
#define NEGV -1.0e9f

// ================= scratch (static device memory; no allocation) =================
__device__ float g_WhhT_enc[H_ * H_];
__device__ float g_WhhT_dec[H_ * H_];
__device__ float g_P_enc[B_ * S_ * H_];
__device__ float g_P_dec[B_ * T_ * H_];
__device__ float g_enc_out[B_ * S_ * H_];
__device__ float g_h_final[B_ * H_];
__device__ float g_Hdec[B_ * T_ * H_];
__device__ float g_comb[B_ * T_ * 2 * H_];
__device__ float g_attn_out[B_ * T_ * H_];
__device__ __half g_Wh[V_ * H_];           // W_out in fp16
__device__ __half g_Ah[B_ * T_ * H_];      // attn_out in fp16

// ================= PTX helpers (sm_80-compatible only; no 'a' features) =================
__device__ __forceinline__ uint32_t smem_u32(const void* p) {
    uint32_t a;
    asm("{ .reg .u64 t; cvta.to.shared.u64 t, %1; cvt.u32.u64 %0, t; }" : "=r"(a) : "l"(p));
    return a;
}
#define CP_ASYNC16(saddr, gaddr) \
    asm volatile("cp.async.cg.shared.global [%0], [%1], 16;" :: "r"(saddr), "l"(gaddr))
#define CP_COMMIT() asm volatile("cp.async.commit_group;")
#define CP_WAIT0()  asm volatile("cp.async.wait_group 0;")
#define LDSM_X4(r, addr) \
    asm volatile("ldmatrix.sync.aligned.m8n8.x4.shared.b16 {%0,%1,%2,%3}, [%4];" \
        : "=r"((r)[0]), "=r"((r)[1]), "=r"((r)[2]), "=r"((r)[3]) : "r"(addr))
#define MMA16816F16(d, a, b) \
    asm volatile("mma.sync.aligned.m16n8k16.row.col.f32.f16.f16.f32 " \
        "{%0,%1,%2,%3}, {%4,%5,%6,%7}, {%8,%9}, {%0,%1,%2,%3};" \
        : "+f"((d)[0]), "+f"((d)[1]), "+f"((d)[2]), "+f"((d)[3]) \
        : "r"((a)[0]), "r"((a)[1]), "r"((a)[2]), "r"((a)[3]), "r"((b)[0]), "r"((b)[1]))

// ================= fp32 -> fp16 convert (vector of 4) =================
__global__ void k_cvt4h(const float4* __restrict__ x, __half* __restrict__ o) {
    int i = blockIdx.x * blockDim.x + threadIdx.x;
    float4 v = x[i];
    __half2* O = (__half2*)(o + (size_t)i * 4);
    O[0] = __halves2half2(__float2half_rn(v.x), __float2half_rn(v.y));
    O[1] = __halves2half2(__float2half_rn(v.z), __float2half_rn(v.w));
}

// ================= mma.sync fp16 logits GEMM =================
// C[4096,32000] = A@W^T + bias ; fp16 inputs, fp32 accumulate.
// CTA tile 128x128, BK=64 (4 chunks over K=256), 8 warps in 4(m)x2(n), warp tile 32x64.
// smem row stride = 144 B (64 fp16 + 8 pad) -> conflict-free ldmatrix phases.
#define LG_STRIDE 144
#define LG_MAT (128 * LG_STRIDE)          // 18432 B per matrix tile
#define LG_A 0
#define LG_W (LG_MAT)
#define LG_BUF (2 * LG_MAT)               // 36864 B per buffer
#define SMEM_LOGITS (2 * LG_BUF)          // 73728 B -> 2+ CTAs/SM

__device__ __forceinline__ void lg_load(
    uint32_t sb, const __half* __restrict__ Ah, const __half* __restrict__ Wh,
    int m0, int n0, int kc, int tid) {
#pragma unroll
    for (int i = 0; i < 4; i++) {
        int idx = tid + i * 256;          // 0..1023
        int r = idx >> 3, c = idx & 7;
        uint32_t soff = r * LG_STRIDE + c * 16;
        size_t ga = (size_t)(m0 + r) * H_ + kc * 64 + c * 8;
        size_t gw = (size_t)(n0 + r) * H_ + kc * 64 + c * 8;
        CP_ASYNC16(sb + LG_A + soff, Ah + ga);
        CP_ASYNC16(sb + LG_W + soff, Wh + gw);
    }
}

__global__ __launch_bounds__(256, 2) void k_logits_mma(
    const __half* __restrict__ Ah, const __half* __restrict__ Wh,
    const float* __restrict__ bias, float* __restrict__ out) {
    extern __shared__ char smem[];
    const uint32_t sbase = smem_u32(smem);
    const int tid = threadIdx.x, wid = tid >> 5, lane = tid & 31;
    const int warp_m = wid & 3, warp_n = wid >> 2;
    const int m0 = blockIdx.x * 128;      // M on x: consecutive CTAs share W tile
    const int n0 = blockIdx.y * 128;

    float acc[2][8][4];
#pragma unroll
    for (int mt = 0; mt < 2; mt++)
#pragma unroll
        for (int nt = 0; nt < 8; nt++)
#pragma unroll
            for (int q = 0; q < 4; q++) acc[mt][nt][q] = 0.0f;

    lg_load(sbase, Ah, Wh, m0, n0, 0, tid);
    CP_COMMIT();
    CP_WAIT0();
    __syncthreads();

    // ldmatrix lane addressing (byte offsets within a tile)
    const int g = lane >> 3, r8 = lane & 7;
    const uint32_t a_off = (uint32_t)(warp_m * 32 + (g & 1) * 8 + r8) * LG_STRIDE +
                           (uint32_t)((g >> 1) * 8) * 2;
    const uint32_t b_off = (uint32_t)(warp_n * 64 + (g >> 1) * 8 + r8) * LG_STRIDE +
                           (uint32_t)((g & 1) * 8) * 2;

    for (int kc = 0; kc < 4; kc++) {
        const uint32_t buf = sbase + (kc & 1) * LG_BUF;
        if (kc < 3) {
            lg_load(sbase + ((kc + 1) & 1) * LG_BUF, Ah, Wh, m0, n0, kc + 1, tid);
            CP_COMMIT();
        }
#pragma unroll
        for (int ks = 0; ks < 4; ks++) {
            const uint32_t koff = (uint32_t)(ks * 16) * 2;
            uint32_t af[2][4], bf[8][2];
#pragma unroll
            for (int p = 0; p < 4; p++) {
                uint32_t t[4];
                LDSM_X4(t, buf + LG_W + b_off + p * (16 * LG_STRIDE) + koff);
                bf[2 * p][0] = t[0]; bf[2 * p][1] = t[1];
                bf[2 * p + 1][0] = t[2]; bf[2 * p + 1][1] = t[3];
            }
#pragma unroll
            for (int mt = 0; mt < 2; mt++)
                LDSM_X4(af[mt], buf + LG_A + a_off + mt * (16 * LG_STRIDE) + koff);
#pragma unroll
            for (int mt = 0; mt < 2; mt++)
#pragma unroll
                for (int nt = 0; nt < 8; nt++) MMA16816F16(acc[mt][nt], af[mt], bf[nt]);
        }
        if (kc < 3) {
            CP_WAIT0();
            __syncthreads();
        }
    }

    // epilogue: c0,c1 -> (row l/4, col 2(l%4)); c2,c3 -> row+8
    const int er = lane >> 2, ec = (lane & 3) * 2;
#pragma unroll
    for (int mt = 0; mt < 2; mt++) {
        const int row0 = m0 + warp_m * 32 + mt * 16 + er;
#pragma unroll
        for (int nt = 0; nt < 8; nt++) {
            const int col0 = n0 + warp_n * 64 + nt * 8 + ec;
            float2 bb = *(const float2*)(bias + col0);
            float2 o0, o1;
            o0.x = acc[mt][nt][0] + bb.x; o0.y = acc[mt][nt][1] + bb.y;
            o1.x = acc[mt][nt][2] + bb.x; o1.y = acc[mt][nt][3] + bb.y;
            *(float2*)(out + (size_t)row0 * V_ + col0) = o0;
            *(float2*)(out + (size_t)(row0 + 8) * V_ + col0) = o1;
        }
    }
}

// ================= tiny transpose: out[k][j] = in[j][k], 256x256 =================
__global__ void k_transpose(const float* __restrict__ in, float* __restrict__ out) {
    int r = blockIdx.x, c = threadIdx.x;
    out[c * H_ + r] = in[r * H_ + c];
}

// ================= generic fp32 SIMT GEMM (small ops only) =================
template <int BM, int BN, int BK, int TM, int TN>
__global__ __launch_bounds__(256) void k_gemm(
    int M, int N, int K,
    const float* __restrict__ A, const int* __restrict__ gidx,
    const float* __restrict__ Bm, float* __restrict__ C,
    const float* __restrict__ bias1, const float* __restrict__ bias2, int act) {
    constexpr int KV = BK / 4;
    constexpr int RPP = 256 / KV;
    constexpr int AP = BM / RPP;
    constexpr int BP = BN / RPP;

    __shared__ __align__(16) float As[2][BK][BM];
    __shared__ __align__(16) float Bs[2][BK][BN];

    const int tid = threadIdx.x;
    const int m0 = blockIdx.y * BM;
    const int n0 = blockIdx.x * BN;
    const int lr = tid / KV;
    const int lk = tid % KV;

    const float* ap[AP];
    const float* bp[BP];
#pragma unroll
    for (int p = 0; p < AP; p++) {
        int gm = m0 + lr + p * RPP;
        int grow = gidx ? gidx[gm] : gm;
        ap[p] = A + (size_t)grow * K + lk * 4;
    }
#pragma unroll
    for (int p = 0; p < BP; p++)
        bp[p] = Bm + (size_t)(n0 + lr + p * RPP) * K + lk * 4;

    float acc[TM][TN];
#pragma unroll
    for (int i = 0; i < TM; i++)
#pragma unroll
        for (int j = 0; j < TN; j++) acc[i][j] = 0.0f;

    float4 ar[AP], br[BP];
#pragma unroll
    for (int p = 0; p < AP; p++) ar[p] = *(const float4*)(ap[p]);
#pragma unroll
    for (int p = 0; p < BP; p++) br[p] = *(const float4*)(bp[p]);
#pragma unroll
    for (int p = 0; p < AP; p++) {
        int m = lr + p * RPP;
        As[0][lk * 4 + 0][m] = ar[p].x; As[0][lk * 4 + 1][m] = ar[p].y;
        As[0][lk * 4 + 2][m] = ar[p].z; As[0][lk * 4 + 3][m] = ar[p].w;
    }
#pragma unroll
    for (int p = 0; p < BP; p++) {
        int n = lr + p * RPP;
        Bs[0][lk * 4 + 0][n] = br[p].x; Bs[0][lk * 4 + 1][n] = br[p].y;
        Bs[0][lk * 4 + 2][n] = br[p].z; Bs[0][lk * 4 + 3][n] = br[p].w;
    }
    __syncthreads();

    const int NT = K / BK;
    const int trow = tid / (BN / TN);
    const int tcol = tid % (BN / TN);

    for (int kt = 0; kt < NT; kt++) {
        const int cur = kt & 1;
        if (kt + 1 < NT) {
#pragma unroll
            for (int p = 0; p < AP; p++) ar[p] = *(const float4*)(ap[p] + (kt + 1) * BK);
#pragma unroll
            for (int p = 0; p < BP; p++) br[p] = *(const float4*)(bp[p] + (kt + 1) * BK);
        }
#pragma unroll
        for (int k = 0; k < BK; k++) {
            float a[TM], bf[TN];
#pragma unroll
            for (int i = 0; i < TM; i += 4) {
                float4 v = *(const float4*)&As[cur][k][trow * TM + i];
                a[i] = v.x; a[i + 1] = v.y; a[i + 2] = v.z; a[i + 3] = v.w;
            }
#pragma unroll
            for (int j = 0; j < TN; j += 4) {
                float4 v = *(const float4*)&Bs[cur][k][tcol * TN + j];
                bf[j] = v.x; bf[j + 1] = v.y; bf[j + 2] = v.z; bf[j + 3] = v.w;
            }
#pragma unroll
            for (int i = 0; i < TM; i++)
#pragma unroll
                for (int j = 0; j < TN; j++) acc[i][j] += a[i] * bf[j];
        }
        if (kt + 1 < NT) {
            const int nxt = cur ^ 1;
#pragma unroll
            for (int p = 0; p < AP; p++) {
                int m = lr + p * RPP;
                As[nxt][lk * 4 + 0][m] = ar[p].x; As[nxt][lk * 4 + 1][m] = ar[p].y;
                As[nxt][lk * 4 + 2][m] = ar[p].z; As[nxt][lk * 4 + 3][m] = ar[p].w;
            }
#pragma unroll
            for (int p = 0; p < BP; p++) {
                int n = lr + p * RPP;
                Bs[nxt][lk * 4 + 0][n] = br[p].x; Bs[nxt][lk * 4 + 1][n] = br[p].y;
                Bs[nxt][lk * 4 + 2][n] = br[p].z; Bs[nxt][lk * 4 + 3][n] = br[p].w;
            }
            __syncthreads();
        }
    }

    float bv[TN];
#pragma unroll
    for (int j = 0; j < TN; j++) {
        int n = n0 + tcol * TN + j;
        float v = bias1 ? bias1[n] : 0.0f;
        if (bias2) v += bias2[n];
        bv[j] = v;
    }
#pragma unroll
    for (int i = 0; i < TM; i++) {
        int m = m0 + trow * TM + i;
        float* crow = C + (size_t)m * N + n0 + tcol * TN;
#pragma unroll
        for (int j = 0; j < TN; j += 4) {
            float4 o;
            o.x = acc[i][j + 0] + bv[j + 0];
            o.y = acc[i][j + 1] + bv[j + 1];
            o.z = acc[i][j + 2] + bv[j + 2];
            o.w = acc[i][j + 3] + bv[j + 3];
            if (act) { o.x = tanhf(o.x); o.y = tanhf(o.y); o.z = tanhf(o.z); o.w = tanhf(o.w); }
            *(float4*)(crow + j) = o;
        }
    }
}

// ================= RNN recurrence: weights resident in smem + registers =================
// One CTA per batch element. Rows 0..WSROWS-1 of WhhT staged in smem (loaded once);
// rows WSROWS..255 held in 32 registers per thread. Zero global weight traffic in loop.
#define WSROWS 224
#define RNN_SMEM ((WSROWS * H_ + H_) * 4)   // 230400 B

__global__ __launch_bounds__(256) void k_rnn(
    const float* __restrict__ P, const float* __restrict__ WT,
    const int* __restrict__ lengths, const float* __restrict__ h0,
    float* __restrict__ outSeq, float* __restrict__ hFin,
    float* __restrict__ combHalf, int steps) {
    extern __shared__ float sm[];
    float* ws = sm;                 // [WSROWS][H_]
    float* hs = sm + WSROWS * H_;   // [H_]
    const int b = blockIdx.x;
    const int j = threadIdx.x;

    // stage weight rows 0..WSROWS-1 into smem (vectorized)
    const float4* WT4 = (const float4*)WT;
    float4* ws4 = (float4*)ws;
    for (int i = j; i < WSROWS * (H_ / 4); i += 256) ws4[i] = WT4[i];
    // tail rows WSROWS..255, column j, in registers
    float wreg[H_ - WSROWS];
#pragma unroll
    for (int i = 0; i < H_ - WSROWS; i++) wreg[i] = WT[(WSROWS + i) * H_ + j];
    hs[j] = h0 ? h0[b * H_ + j] : 0.0f;
    __syncthreads();

    const int len = lengths ? lengths[b] : steps;
    const float* Pb = P + (size_t)b * steps * H_;
    float* Ob = outSeq + (size_t)b * steps * H_;

    for (int t = 0; t < steps; t++) {
        float pv = Pb[t * H_ + j];          // prefetch early
        float a0 = 0.f, a1 = 0.f, a2 = 0.f, a3 = 0.f;
#pragma unroll 4
        for (int k = 0; k < WSROWS; k += 4) {
            float4 h4 = *(const float4*)&hs[k];
            const float* wk = ws + k * H_ + j;
            a0 += h4.x * wk[0];
            a1 += h4.y * wk[H_];
            a2 += h4.z * wk[2 * H_];
            a3 += h4.w * wk[3 * H_];
        }
#pragma unroll
        for (int i = 0; i < H_ - WSROWS; i += 4) {
            float4 h4 = *(const float4*)&hs[WSROWS + i];
            a0 += h4.x * wreg[i];     a1 += h4.y * wreg[i + 1];
            a2 += h4.z * wreg[i + 2]; a3 += h4.w * wreg[i + 3];
        }
        float hn = tanhf(pv + ((a0 + a1) + (a2 + a3)));
        bool valid = t < len;
        __syncthreads();
        if (valid) hs[j] = hn;
        Ob[t * H_ + j] = valid ? hn : 0.0f;
        if (combHalf)
            combHalf[((size_t)(b * steps + t)) * (2 * H_) + H_ + j] = hn;
        __syncthreads();
    }
    if (hFin) hFin[b * H_ + j] = hs[j];
}

// ================= fused attention: scores -> softmax -> context =================
__global__ __launch_bounds__(256) void k_attn(
    const float* __restrict__ Hdec, const float* __restrict__ enc,
    const int* __restrict__ idx_de, float* __restrict__ comb) {
    const int b = blockIdx.x;
    const int t0 = blockIdx.y * 16;
    const int tid = threadIdx.x;
    __shared__ __align__(16) float hs[16][H_];
    __shared__ float sc[16][132];
    __shared__ int msk[S_];

    const float4* Hb4 = (const float4*)(Hdec + ((size_t)b * T_ + t0) * H_);
#pragma unroll
    for (int i = 0; i < 4; i++)
        ((float4*)hs)[tid + i * 256] = Hb4[tid + i * 256];
    if (tid < S_) msk[tid] = idx_de[b * S_ + tid];
    __syncthreads();

    const float* Eb = enc + (size_t)b * S_ * H_;
    {
        const int ti = tid >> 4, sg = tid & 15;
        const float4* h4 = (const float4*)hs[ti];
        for (int r = 0; r < 8; r++) {
            int s = r * 16 + sg;
            const float4* e4 = (const float4*)(Eb + s * H_);
            float a0 = 0.f, a1 = 0.f, a2 = 0.f, a3 = 0.f;
#pragma unroll 8
            for (int k = 0; k < H_ / 4; k++) {
                float4 e = e4[k], h = h4[k];
                a0 += e.x * h.x; a1 += e.y * h.y;
                a2 += e.z * h.z; a3 += e.w * h.w;
            }
            sc[ti][s] = (msk[s] == 0) ? NEGV : ((a0 + a1) + (a2 + a3));
        }
    }
    __syncthreads();
    {
        const int w = tid >> 5, lane = tid & 31;
#pragma unroll
        for (int rr = 0; rr < 2; rr++) {
            int row = w * 2 + rr;
            float v0 = sc[row][lane], v1 = sc[row][lane + 32];
            float v2 = sc[row][lane + 64], v3 = sc[row][lane + 96];
            float m = fmaxf(fmaxf(v0, v1), fmaxf(v2, v3));
#pragma unroll
            for (int o = 16; o > 0; o >>= 1)
                m = fmaxf(m, __shfl_xor_sync(0xffffffffu, m, o));
            float e0 = expf(v0 - m), e1 = expf(v1 - m);
            float e2 = expf(v2 - m), e3 = expf(v3 - m);
            float sum = (e0 + e1) + (e2 + e3);
#pragma unroll
            for (int o = 16; o > 0; o >>= 1)
                sum += __shfl_xor_sync(0xffffffffu, sum, o);
            float inv = 1.0f / sum;
            sc[row][lane] = e0 * inv; sc[row][lane + 32] = e1 * inv;
            sc[row][lane + 64] = e2 * inv; sc[row][lane + 96] = e3 * inv;
        }
    }
    __syncthreads();
    {
        const int ti = tid & 15, jg = tid >> 4;
        float4 c0 = {0, 0, 0, 0}, c1 = c0, c2 = c0, c3 = c0;
        for (int s = 0; s < S_; s++) {
            float p = sc[ti][s];
            const float4* e4 = (const float4*)(Eb + s * H_ + jg * 16);
            float4 e0 = e4[0], e1 = e4[1], e2 = e4[2], e3 = e4[3];
            c0.x += p * e0.x; c0.y += p * e0.y; c0.z += p * e0.z; c0.w += p * e0.w;
            c1.x += p * e1.x; c1.y += p * e1.y; c1.z += p * e1.z; c1.w += p * e1.w;
            c2.x += p * e2.x; c2.y += p * e2.y; c2.z += p * e2.z; c2.w += p * e2.w;
            c3.x += p * e3.x; c3.y += p * e3.y; c3.z += p * e3.z; c3.w += p * e3.w;
        }
        float* dst = comb + ((size_t)(b * T_ + t0 + ti)) * (2 * H_) + jg * 16;
        ((float4*)dst)[0] = c0; ((float4*)dst)[1] = c1;
        ((float4*)dst)[2] = c2; ((float4*)dst)[3] = c3;
    }
}

// ================= launch =================
extern "C" void kernel_launch(void* const* d_in, const int* in_sizes, int n_in,
                              void* d_out, int out_size) {
    const int* indices_de = (const int*)d_in[0];
    const int* lengths_de = (const int*)d_in[1];
    const int* indices_en = (const int*)d_in[2];
    const float* emb_enc = (const float*)d_in[4];
    const float* emb_dec = (const float*)d_in[5];
    const float* W_ih_enc = (const float*)d_in[6];
    const float* W_hh_enc = (const float*)d_in[7];
    const float* b_ih_enc = (const float*)d_in[8];
    const float* b_hh_enc = (const float*)d_in[9];
    const float* W_ih_dec = (const float*)d_in[10];
    const float* W_hh_dec = (const float*)d_in[11];
    const float* b_ih_dec = (const float*)d_in[12];
    const float* b_hh_dec = (const float*)d_in[13];
    const float* W_attn = (const float*)d_in[14];
    const float* b_attn = (const float*)d_in[15];
    const float* W_out = (const float*)d_in[16];
    const float* b_out = (const float*)d_in[17];
    float* out = (float*)d_out;

    float *pWTe, *pWTd, *pPe, *pPd, *pEnc, *pHf, *pHd, *pComb, *pAo;
    __half *pWh, *pAh;
    cudaGetSymbolAddress((void**)&pWTe, g_WhhT_enc);
    cudaGetSymbolAddress((void**)&pWTd, g_WhhT_dec);
    cudaGetSymbolAddress((void**)&pPe, g_P_enc);
    cudaGetSymbolAddress((void**)&pPd, g_P_dec);
    cudaGetSymbolAddress((void**)&pEnc, g_enc_out);
    cudaGetSymbolAddress((void**)&pHf, g_h_final);
    cudaGetSymbolAddress((void**)&pHd, g_Hdec);
    cudaGetSymbolAddress((void**)&pComb, g_comb);
    cudaGetSymbolAddress((void**)&pAo, g_attn_out);
    cudaGetSymbolAddress((void**)&pWh, g_Wh);
    cudaGetSymbolAddress((void**)&pAh, g_Ah);

    cudaFuncSetAttribute(k_logits_mma, cudaFuncAttributeMaxDynamicSharedMemorySize,
                         SMEM_LOGITS);
    cudaFuncSetAttribute(k_rnn, cudaFuncAttributeMaxDynamicSharedMemorySize,
                         RNN_SMEM);

    // 1. transpose recurrent weights; convert W_out to fp16
    k_transpose<<<H_, H_>>>(W_hh_enc, pWTe);
    k_transpose<<<H_, H_>>>(W_hh_dec, pWTd);
    k_cvt4h<<<(V_ * H_ / 4) / 256, 256>>>((const float4*)W_out, pWh);

    // 2. batched input projections (embedding gather fused into GEMM)
    k_gemm<64, 64, 16, 4, 4><<<dim3(H_ / 64, (B_ * S_) / 64), 256>>>(
        B_ * S_, H_, E_, emb_enc, indices_de, W_ih_enc, pPe, b_ih_enc, b_hh_enc, 0);
    k_gemm<64, 64, 16, 4, 4><<<dim3(H_ / 64, (B_ * T_) / 64), 256>>>(
        B_ * T_, H_, E_, emb_dec, indices_en, W_ih_dec, pPd, b_ih_dec, b_hh_dec, 0);

    // 3. sequential recurrences (weights SM-resident)
    k_rnn<<<B_, 256, RNN_SMEM>>>(pPe, pWTe, lengths_de, nullptr, pEnc, pHf, nullptr, S_);
    k_rnn<<<B_, 256, RNN_SMEM>>>(pPd, pWTd, nullptr, pHf, pHd, nullptr, pComb, T_);

    // 4. attention -> context into comb[:, 0:H]
    k_attn<<<dim3(B_, T_ / 16), 256>>>(pHd, pEnc, indices_de, pComb);

    // 5. attn_out = tanh([context|h] @ W_attn^T + b_attn)
    k_gemm<64, 64, 16, 4, 4><<<dim3(H_ / 64, (B_ * T_) / 64), 256>>>(
        B_ * T_, H_, 2 * H_, pComb, nullptr, W_attn, pAo, b_attn, nullptr, 1);

    // 6. convert attn_out to fp16, then mma.sync fp16 logits GEMM
    k_cvt4h<<<(B_ * T_ * H_ / 4) / 256, 256>>>((const float4*)pAo, pAh);
    k_logits_mma<<<dim3((B_ * T_) / 128, V_ / 128), 256, SMEM_LOGITS>>>(
        pAh, pWh, b_out, out);
}

// round 8
// speedup vs baseline: 4.2051x; 1.1583x over previous
#include <cuda_runtime.h>
#include <cuda_fp16.h>
#include <cstdint>
#include <cstddef>

#define B_ 32
#define S_ 128
#define T_ 128
#define V_ 32000
#define E_ 256
#define H_ 256
#define NEGV -1.0e9f

// ================= scratch (static device memory; no allocation) =================
__device__ float g_P_enc[B_ * S_ * H_];
__device__ float g_P_dec[B_ * T_ * H_];
__device__ float g_enc_out[B_ * S_ * H_];
__device__ float g_h_final[B_ * H_];
__device__ float g_Hdec[B_ * T_ * H_];
__device__ float g_comb[B_ * T_ * 2 * H_];
__device__ __half g_Wh[V_ * H_];           // W_out in fp16
__device__ __half g_Ah[B_ * T_ * H_];      // attn_out in fp16

// ================= PTX helpers (sm_80-compatible only; no 'a' features) =================
__device__ __forceinline__ uint32_t smem_u32(const void* p) {
    uint32_t a;
    asm("{ .reg .u64 t; cvta.to.shared.u64 t, %1; cvt.u32.u64 %0, t; }" : "=r"(a) : "l"(p));
    return a;
}
#define CP_ASYNC16(saddr, gaddr) \
    asm volatile("cp.async.cg.shared.global [%0], [%1], 16;" :: "r"(saddr), "l"(gaddr))
#define CP_COMMIT() asm volatile("cp.async.commit_group;")
#define CP_WAIT0()  asm volatile("cp.async.wait_group 0;")
#define LDSM_X4(r, addr) \
    asm volatile("ldmatrix.sync.aligned.m8n8.x4.shared.b16 {%0,%1,%2,%3}, [%4];" \
        : "=r"((r)[0]), "=r"((r)[1]), "=r"((r)[2]), "=r"((r)[3]) : "r"(addr))
#define MMA16816F16(d, a, b) \
    asm volatile("mma.sync.aligned.m16n8k16.row.col.f32.f16.f16.f32 " \
        "{%0,%1,%2,%3}, {%4,%5,%6,%7}, {%8,%9}, {%0,%1,%2,%3};" \
        : "+f"((d)[0]), "+f"((d)[1]), "+f"((d)[2]), "+f"((d)[3]) \
        : "r"((a)[0]), "r"((a)[1]), "r"((a)[2]), "r"((a)[3]), "r"((b)[0]), "r"((b)[1]))

// ================= fp32 -> fp16 convert (vector of 4) =================
__global__ void k_cvt4h(const float4* __restrict__ x, __half* __restrict__ o) {
    int i = blockIdx.x * blockDim.x + threadIdx.x;
    float4 v = x[i];
    __half2* O = (__half2*)(o + (size_t)i * 4);
    O[0] = __halves2half2(__float2half_rn(v.x), __float2half_rn(v.y));
    O[1] = __halves2half2(__float2half_rn(v.z), __float2half_rn(v.w));
}

// ================= mma.sync fp16 logits GEMM =================
// C[4096,32000] = A@W^T + bias ; fp16 inputs, fp32 accumulate.
// CTA tile 128x128, BK=64 (4 chunks over K=256), 8 warps in 4(m)x2(n), warp tile 32x64.
#define LG_STRIDE 144
#define LG_MAT (128 * LG_STRIDE)
#define LG_A 0
#define LG_W (LG_MAT)
#define LG_BUF (2 * LG_MAT)               // 36864 B per buffer
#define SMEM_LOGITS (2 * LG_BUF)          // 73728 B

__device__ __forceinline__ void lg_load(
    uint32_t sb, const __half* __restrict__ Ah, const __half* __restrict__ Wh,
    int m0, int n0, int kc, int tid) {
#pragma unroll
    for (int i = 0; i < 4; i++) {
        int idx = tid + i * 256;
        int r = idx >> 3, c = idx & 7;
        uint32_t soff = r * LG_STRIDE + c * 16;
        size_t ga = (size_t)(m0 + r) * H_ + kc * 64 + c * 8;
        size_t gw = (size_t)(n0 + r) * H_ + kc * 64 + c * 8;
        CP_ASYNC16(sb + LG_A + soff, Ah + ga);
        CP_ASYNC16(sb + LG_W + soff, Wh + gw);
    }
}

__global__ __launch_bounds__(256, 2) void k_logits_mma(
    const __half* __restrict__ Ah, const __half* __restrict__ Wh,
    const float* __restrict__ bias, float* __restrict__ out) {
    extern __shared__ char smem[];
    const uint32_t sbase = smem_u32(smem);
    const int tid = threadIdx.x, wid = tid >> 5, lane = tid & 31;
    const int warp_m = wid & 3, warp_n = wid >> 2;
    const int m0 = blockIdx.x * 128;
    const int n0 = blockIdx.y * 128;

    float acc[2][8][4];
#pragma unroll
    for (int mt = 0; mt < 2; mt++)
#pragma unroll
        for (int nt = 0; nt < 8; nt++)
#pragma unroll
            for (int q = 0; q < 4; q++) acc[mt][nt][q] = 0.0f;

    lg_load(sbase, Ah, Wh, m0, n0, 0, tid);
    CP_COMMIT();
    CP_WAIT0();
    __syncthreads();

    const int g = lane >> 3, r8 = lane & 7;
    const uint32_t a_off = (uint32_t)(warp_m * 32 + (g & 1) * 8 + r8) * LG_STRIDE +
                           (uint32_t)((g >> 1) * 8) * 2;
    const uint32_t b_off = (uint32_t)(warp_n * 64 + (g >> 1) * 8 + r8) * LG_STRIDE +
                           (uint32_t)((g & 1) * 8) * 2;

    for (int kc = 0; kc < 4; kc++) {
        const uint32_t buf = sbase + (kc & 1) * LG_BUF;
        if (kc < 3) {
            lg_load(sbase + ((kc + 1) & 1) * LG_BUF, Ah, Wh, m0, n0, kc + 1, tid);
            CP_COMMIT();
        }
#pragma unroll
        for (int ks = 0; ks < 4; ks++) {
            const uint32_t koff = (uint32_t)(ks * 16) * 2;
            uint32_t af[2][4], bf[8][2];
#pragma unroll
            for (int p = 0; p < 4; p++) {
                uint32_t t[4];
                LDSM_X4(t, buf + LG_W + b_off + p * (16 * LG_STRIDE) + koff);
                bf[2 * p][0] = t[0]; bf[2 * p][1] = t[1];
                bf[2 * p + 1][0] = t[2]; bf[2 * p + 1][1] = t[3];
            }
#pragma unroll
            for (int mt = 0; mt < 2; mt++)
                LDSM_X4(af[mt], buf + LG_A + a_off + mt * (16 * LG_STRIDE) + koff);
#pragma unroll
            for (int mt = 0; mt < 2; mt++)
#pragma unroll
                for (int nt = 0; nt < 8; nt++) MMA16816F16(acc[mt][nt], af[mt], bf[nt]);
        }
        if (kc < 3) {
            CP_WAIT0();
            __syncthreads();
        }
    }

    const int er = lane >> 2, ec = (lane & 3) * 2;
#pragma unroll
    for (int mt = 0; mt < 2; mt++) {
        const int row0 = m0 + warp_m * 32 + mt * 16 + er;
#pragma unroll
        for (int nt = 0; nt < 8; nt++) {
            const int col0 = n0 + warp_n * 64 + nt * 8 + ec;
            float2 bb = *(const float2*)(bias + col0);
            float2 o0, o1;
            o0.x = acc[mt][nt][0] + bb.x; o0.y = acc[mt][nt][1] + bb.y;
            o1.x = acc[mt][nt][2] + bb.x; o1.y = acc[mt][nt][3] + bb.y;
            *(float2*)(out + (size_t)row0 * V_ + col0) = o0;
            *(float2*)(out + (size_t)(row0 + 8) * V_ + col0) = o1;
        }
    }
}

// ================= generic fp32 SIMT GEMM (small ops only) =================
// If Ch != nullptr, writes fp16 output there instead of fp32 C.
template <int BM, int BN, int BK, int TM, int TN>
__global__ __launch_bounds__(256) void k_gemm(
    int M, int N, int K,
    const float* __restrict__ A, const int* __restrict__ gidx,
    const float* __restrict__ Bm, float* __restrict__ C,
    const float* __restrict__ bias1, const float* __restrict__ bias2, int act,
    __half* __restrict__ Ch) {
    constexpr int KV = BK / 4;
    constexpr int RPP = 256 / KV;
    constexpr int AP = BM / RPP;
    constexpr int BP = BN / RPP;

    __shared__ __align__(16) float As[2][BK][BM];
    __shared__ __align__(16) float Bs[2][BK][BN];

    const int tid = threadIdx.x;
    const int m0 = blockIdx.y * BM;
    const int n0 = blockIdx.x * BN;
    const int lr = tid / KV;
    const int lk = tid % KV;

    const float* ap[AP];
    const float* bp[BP];
#pragma unroll
    for (int p = 0; p < AP; p++) {
        int gm = m0 + lr + p * RPP;
        int grow = gidx ? gidx[gm] : gm;
        ap[p] = A + (size_t)grow * K + lk * 4;
    }
#pragma unroll
    for (int p = 0; p < BP; p++)
        bp[p] = Bm + (size_t)(n0 + lr + p * RPP) * K + lk * 4;

    float acc[TM][TN];
#pragma unroll
    for (int i = 0; i < TM; i++)
#pragma unroll
        for (int j = 0; j < TN; j++) acc[i][j] = 0.0f;

    float4 ar[AP], br[BP];
#pragma unroll
    for (int p = 0; p < AP; p++) ar[p] = *(const float4*)(ap[p]);
#pragma unroll
    for (int p = 0; p < BP; p++) br[p] = *(const float4*)(bp[p]);
#pragma unroll
    for (int p = 0; p < AP; p++) {
        int m = lr + p * RPP;
        As[0][lk * 4 + 0][m] = ar[p].x; As[0][lk * 4 + 1][m] = ar[p].y;
        As[0][lk * 4 + 2][m] = ar[p].z; As[0][lk * 4 + 3][m] = ar[p].w;
    }
#pragma unroll
    for (int p = 0; p < BP; p++) {
        int n = lr + p * RPP;
        Bs[0][lk * 4 + 0][n] = br[p].x; Bs[0][lk * 4 + 1][n] = br[p].y;
        Bs[0][lk * 4 + 2][n] = br[p].z; Bs[0][lk * 4 + 3][n] = br[p].w;
    }
    __syncthreads();

    const int NT = K / BK;
    const int trow = tid / (BN / TN);
    const int tcol = tid % (BN / TN);

    for (int kt = 0; kt < NT; kt++) {
        const int cur = kt & 1;
        if (kt + 1 < NT) {
#pragma unroll
            for (int p = 0; p < AP; p++) ar[p] = *(const float4*)(ap[p] + (kt + 1) * BK);
#pragma unroll
            for (int p = 0; p < BP; p++) br[p] = *(const float4*)(bp[p] + (kt + 1) * BK);
        }
#pragma unroll
        for (int k = 0; k < BK; k++) {
            float a[TM], bf[TN];
#pragma unroll
            for (int i = 0; i < TM; i += 4) {
                float4 v = *(const float4*)&As[cur][k][trow * TM + i];
                a[i] = v.x; a[i + 1] = v.y; a[i + 2] = v.z; a[i + 3] = v.w;
            }
#pragma unroll
            for (int j = 0; j < TN; j += 4) {
                float4 v = *(const float4*)&Bs[cur][k][tcol * TN + j];
                bf[j] = v.x; bf[j + 1] = v.y; bf[j + 2] = v.z; bf[j + 3] = v.w;
            }
#pragma unroll
            for (int i = 0; i < TM; i++)
#pragma unroll
                for (int j = 0; j < TN; j++) acc[i][j] += a[i] * bf[j];
        }
        if (kt + 1 < NT) {
            const int nxt = cur ^ 1;
#pragma unroll
            for (int p = 0; p < AP; p++) {
                int m = lr + p * RPP;
                As[nxt][lk * 4 + 0][m] = ar[p].x; As[nxt][lk * 4 + 1][m] = ar[p].y;
                As[nxt][lk * 4 + 2][m] = ar[p].z; As[nxt][lk * 4 + 3][m] = ar[p].w;
            }
#pragma unroll
            for (int p = 0; p < BP; p++) {
                int n = lr + p * RPP;
                Bs[nxt][lk * 4 + 0][n] = br[p].x; Bs[nxt][lk * 4 + 1][n] = br[p].y;
                Bs[nxt][lk * 4 + 2][n] = br[p].z; Bs[nxt][lk * 4 + 3][n] = br[p].w;
            }
            __syncthreads();
        }
    }

    float bv[TN];
#pragma unroll
    for (int j = 0; j < TN; j++) {
        int n = n0 + tcol * TN + j;
        float v = bias1 ? bias1[n] : 0.0f;
        if (bias2) v += bias2[n];
        bv[j] = v;
    }
#pragma unroll
    for (int i = 0; i < TM; i++) {
        int m = m0 + trow * TM + i;
#pragma unroll
        for (int j = 0; j < TN; j += 4) {
            float4 o;
            o.x = acc[i][j + 0] + bv[j + 0];
            o.y = acc[i][j + 1] + bv[j + 1];
            o.z = acc[i][j + 2] + bv[j + 2];
            o.w = acc[i][j + 3] + bv[j + 3];
            if (act) { o.x = tanhf(o.x); o.y = tanhf(o.y); o.z = tanhf(o.z); o.w = tanhf(o.w); }
            if (Ch) {
                __half* crow = Ch + (size_t)m * N + n0 + tcol * TN;
                *(__half2*)(crow + j) = __halves2half2(__float2half_rn(o.x), __float2half_rn(o.y));
                *(__half2*)(crow + j + 2) = __halves2half2(__float2half_rn(o.z), __float2half_rn(o.w));
            } else {
                float* crow = C + (size_t)m * N + n0 + tcol * TN;
                *(float4*)(crow + j) = o;
            }
        }
    }
}

// ================= RNN recurrence: weights SM-resident (fp32 regs + fp16 smem) ==========
// One CTA per batch element. out_j = tanh(P + sum_k h[k]*W[j][k]).
// Rows k in [0,64): exact fp32 in registers. Rows k in [64,256): fp16 half2-packed
// in smem (halves per-step smem traffic vs fp32). fp32 accumulation throughout.
// h double-buffered -> single __syncthreads per step.
#define RNN_WH2 (96 * 256)                       // half2 count
#define RNN_SMEM (RNN_WH2 * 4 + 2 * H_ * 4)      // 100352 B

__global__ __launch_bounds__(256) void k_rnn(
    const float* __restrict__ P, const float* __restrict__ W,   // W = W_hh [H][H]
    const int* __restrict__ lengths, const float* __restrict__ h0,
    float* __restrict__ outSeq, float* __restrict__ hFin,
    float* __restrict__ combHalf, int steps) {
    extern __shared__ float sm[];
    __half2* wsh = (__half2*)sm;                 // [96][256]
    float* hs = sm + RNN_WH2;                    // 2 buffers of H_
    const int b = blockIdx.x;
    const int j = threadIdx.x;

    // stage: thread j owns row j of W (contiguous in k)
    const float* wrow = W + (size_t)j * H_;
    float wreg[64];
#pragma unroll
    for (int i = 0; i < 64; i += 4) {
        float4 w4 = *(const float4*)(wrow + i);
        wreg[i] = w4.x; wreg[i + 1] = w4.y; wreg[i + 2] = w4.z; wreg[i + 3] = w4.w;
    }
#pragma unroll 8
    for (int i = 0; i < 96; i++) {
        float2 w2 = *(const float2*)(wrow + 64 + 2 * i);
        wsh[i * 256 + j] = __floats2half2_rn(w2.x, w2.y);
    }
    hs[j] = h0 ? h0[b * H_ + j] : 0.0f;
    __syncthreads();

    const int len = lengths ? lengths[b] : steps;
    const float* Pb = P + (size_t)b * steps * H_;
    float* Ob = outSeq + (size_t)b * steps * H_;
    int cur = 0;

    for (int t = 0; t < steps; t++) {
        const float* hc = hs + cur * H_;
        float* hnx = hs + (cur ^ 1) * H_;
        float pv = Pb[t * H_ + j];
        float a0 = 0.f, a1 = 0.f, a2 = 0.f, a3 = 0.f;
#pragma unroll
        for (int k = 0; k < 64; k += 4) {
            float4 h4 = *(const float4*)(hc + k);
            a0 += h4.x * wreg[k];     a1 += h4.y * wreg[k + 1];
            a2 += h4.z * wreg[k + 2]; a3 += h4.w * wreg[k + 3];
        }
#pragma unroll
        for (int i = 0; i < 96; i += 2) {
            float4 h4 = *(const float4*)(hc + 64 + 2 * i);
            float2 fa = __half22float2(wsh[i * 256 + j]);
            float2 fb = __half22float2(wsh[(i + 1) * 256 + j]);
            a0 += h4.x * fa.x; a1 += h4.y * fa.y;
            a2 += h4.z * fb.x; a3 += h4.w * fb.y;
        }
        float hv = tanhf(pv + ((a0 + a1) + (a2 + a3)));
        bool valid = t < len;
        hnx[j] = valid ? hv : hc[j];
        Ob[t * H_ + j] = valid ? hv : 0.0f;
        if (combHalf)
            combHalf[((size_t)(b * steps + t)) * (2 * H_) + H_ + j] = hv;
        __syncthreads();
        cur ^= 1;
    }
    if (hFin) hFin[b * H_ + j] = hs[cur * H_ + j];
}

// ================= fused attention: scores -> softmax -> context =================
__global__ __launch_bounds__(256) void k_attn(
    const float* __restrict__ Hdec, const float* __restrict__ enc,
    const int* __restrict__ idx_de, float* __restrict__ comb) {
    const int b = blockIdx.x;
    const int t0 = blockIdx.y * 16;
    const int tid = threadIdx.x;
    __shared__ __align__(16) float hs[16][H_];
    __shared__ float sc[16][132];
    __shared__ int msk[S_];

    const float4* Hb4 = (const float4*)(Hdec + ((size_t)b * T_ + t0) * H_);
#pragma unroll
    for (int i = 0; i < 4; i++)
        ((float4*)hs)[tid + i * 256] = Hb4[tid + i * 256];
    if (tid < S_) msk[tid] = idx_de[b * S_ + tid];
    __syncthreads();

    const float* Eb = enc + (size_t)b * S_ * H_;
    {
        const int ti = tid >> 4, sg = tid & 15;
        const float4* h4 = (const float4*)hs[ti];
        for (int r = 0; r < 8; r++) {
            int s = r * 16 + sg;
            const float4* e4 = (const float4*)(Eb + s * H_);
            float a0 = 0.f, a1 = 0.f, a2 = 0.f, a3 = 0.f;
#pragma unroll 8
            for (int k = 0; k < H_ / 4; k++) {
                float4 e = e4[k], h = h4[k];
                a0 += e.x * h.x; a1 += e.y * h.y;
                a2 += e.z * h.z; a3 += e.w * h.w;
            }
            sc[ti][s] = (msk[s] == 0) ? NEGV : ((a0 + a1) + (a2 + a3));
        }
    }
    __syncthreads();
    {
        const int w = tid >> 5, lane = tid & 31;
#pragma unroll
        for (int rr = 0; rr < 2; rr++) {
            int row = w * 2 + rr;
            float v0 = sc[row][lane], v1 = sc[row][lane + 32];
            float v2 = sc[row][lane + 64], v3 = sc[row][lane + 96];
            float m = fmaxf(fmaxf(v0, v1), fmaxf(v2, v3));
#pragma unroll
            for (int o = 16; o > 0; o >>= 1)
                m = fmaxf(m, __shfl_xor_sync(0xffffffffu, m, o));
            float e0 = expf(v0 - m), e1 = expf(v1 - m);
            float e2 = expf(v2 - m), e3 = expf(v3 - m);
            float sum = (e0 + e1) + (e2 + e3);
#pragma unroll
            for (int o = 16; o > 0; o >>= 1)
                sum += __shfl_xor_sync(0xffffffffu, sum, o);
            float inv = 1.0f / sum;
            sc[row][lane] = e0 * inv; sc[row][lane + 32] = e1 * inv;
            sc[row][lane + 64] = e2 * inv; sc[row][lane + 96] = e3 * inv;
        }
    }
    __syncthreads();
    {
        const int ti = tid & 15, jg = tid >> 4;
        float4 c0 = {0, 0, 0, 0}, c1 = c0, c2 = c0, c3 = c0;
        for (int s = 0; s < S_; s++) {
            float p = sc[ti][s];
            const float4* e4 = (const float4*)(Eb + s * H_ + jg * 16);
            float4 e0 = e4[0], e1 = e4[1], e2 = e4[2], e3 = e4[3];
            c0.x += p * e0.x; c0.y += p * e0.y; c0.z += p * e0.z; c0.w += p * e0.w;
            c1.x += p * e1.x; c1.y += p * e1.y; c1.z += p * e1.z; c1.w += p * e1.w;
            c2.x += p * e2.x; c2.y += p * e2.y; c2.z += p * e2.z; c2.w += p * e2.w;
            c3.x += p * e3.x; c3.y += p * e3.y; c3.z += p * e3.z; c3.w += p * e3.w;
        }
        float* dst = comb + ((size_t)(b * T_ + t0 + ti)) * (2 * H_) + jg * 16;
        ((float4*)dst)[0] = c0; ((float4*)dst)[1] = c1;
        ((float4*)dst)[2] = c2; ((float4*)dst)[3] = c3;
    }
}

// ================= launch =================
extern "C" void kernel_launch(void* const* d_in, const int* in_sizes, int n_in,
                              void* d_out, int out_size) {
    const int* indices_de = (const int*)d_in[0];
    const int* lengths_de = (const int*)d_in[1];
    const int* indices_en = (const int*)d_in[2];
    const float* emb_enc = (const float*)d_in[4];
    const float* emb_dec = (const float*)d_in[5];
    const float* W_ih_enc = (const float*)d_in[6];
    const float* W_hh_enc = (const float*)d_in[7];
    const float* b_ih_enc = (const float*)d_in[8];
    const float* b_hh_enc = (const float*)d_in[9];
    const float* W_ih_dec = (const float*)d_in[10];
    const float* W_hh_dec = (const float*)d_in[11];
    const float* b_ih_dec = (const float*)d_in[12];
    const float* b_hh_dec = (const float*)d_in[13];
    const float* W_attn = (const float*)d_in[14];
    const float* b_attn = (const float*)d_in[15];
    const float* W_out = (const float*)d_in[16];
    const float* b_out = (const float*)d_in[17];
    float* out = (float*)d_out;

    float *pPe, *pPd, *pEnc, *pHf, *pHd, *pComb;
    __half *pWh, *pAh;
    cudaGetSymbolAddress((void**)&pPe, g_P_enc);
    cudaGetSymbolAddress((void**)&pPd, g_P_dec);
    cudaGetSymbolAddress((void**)&pEnc, g_enc_out);
    cudaGetSymbolAddress((void**)&pHf, g_h_final);
    cudaGetSymbolAddress((void**)&pHd, g_Hdec);
    cudaGetSymbolAddress((void**)&pComb, g_comb);
    cudaGetSymbolAddress((void**)&pWh, g_Wh);
    cudaGetSymbolAddress((void**)&pAh, g_Ah);

    cudaFuncSetAttribute(k_logits_mma, cudaFuncAttributeMaxDynamicSharedMemorySize,
                         SMEM_LOGITS);
    cudaFuncSetAttribute(k_rnn, cudaFuncAttributeMaxDynamicSharedMemorySize,
                         RNN_SMEM);

    // 1. convert W_out to fp16
    k_cvt4h<<<(V_ * H_ / 4) / 256, 256>>>((const float4*)W_out, pWh);

    // 2. batched input projections (embedding gather fused into GEMM)
    k_gemm<64, 64, 16, 4, 4><<<dim3(H_ / 64, (B_ * S_) / 64), 256>>>(
        B_ * S_, H_, E_, emb_enc, indices_de, W_ih_enc, pPe, b_ih_enc, b_hh_enc, 0, nullptr);
    k_gemm<64, 64, 16, 4, 4><<<dim3(H_ / 64, (B_ * T_) / 64), 256>>>(
        B_ * T_, H_, E_, emb_dec, indices_en, W_ih_dec, pPd, b_ih_dec, b_hh_dec, 0, nullptr);

    // 3. sequential recurrences (weights SM-resident, staged from original layout)
    k_rnn<<<B_, 256, RNN_SMEM>>>(pPe, W_hh_enc, lengths_de, nullptr, pEnc, pHf, nullptr, S_);
    k_rnn<<<B_, 256, RNN_SMEM>>>(pPd, W_hh_dec, nullptr, pHf, pHd, nullptr, pComb, T_);

    // 4. attention -> context into comb[:, 0:H]
    k_attn<<<dim3(B_, T_ / 16), 256>>>(pHd, pEnc, indices_de, pComb);

    // 5. attn_out = tanh([context|h] @ W_attn^T + b_attn), written directly as fp16
    k_gemm<64, 64, 16, 4, 4><<<dim3(H_ / 64, (B_ * T_) / 64), 256>>>(
        B_ * T_, H_, 2 * H_, pComb, nullptr, W_attn, nullptr, b_attn, nullptr, 1, pAh);

    // 6. mma.sync fp16 logits GEMM
    k_logits_mma<<<dim3((B_ * T_) / 128, V_ / 128), 256, SMEM_LOGITS>>>(
        pAh, pWh, b_out, out);
}